// round 2
// baseline (speedup 1.0000x reference)
#include <cuda_runtime.h>
#include <math.h>

#define NVAR 4
#define BB   4
#define TT   512
#define DD   512
#define HH   8
#define MROWS (NVAR*BB*TT)   // 8192

// Scratch (alloc-free rule: __device__ globals)
__device__ float g_q[MROWS*DD];
__device__ float g_k[MROWS*DD];
__device__ float g_v[MROWS*DD];
__device__ float g_ctx[MROWS*DD];
__device__ float g_res[MROWS*DD];

// ---------------------------------------------------------------------------
// Tiled SGEMM body: C[128x64 tile] = scale*(A@B) + bias (+ resid)
// A: [M,512] row-major, B: [512,512] row-major, C: [M,512]
// 256 threads, BM=128, BN=64, BK=16, micro-tile 8x4.
// ---------------------------------------------------------------------------
__device__ __forceinline__ void sgemm_tile(const float* __restrict__ A,
                                           const float* __restrict__ Bm,
                                           float* __restrict__ C,
                                           const float* __restrict__ bias,
                                           const float* __restrict__ resid,
                                           float scale)
{
    __shared__ float As[16][132];  // [k][m], padded
    __shared__ float Bs[16][68];   // [k][n], padded (16B-aligned rows)

    const int tid = threadIdx.x;
    const int tx = tid & 15;   // n direction (x4)
    const int ty = tid >> 4;   // m direction (x8)
    const int bm0 = blockIdx.y * 128;
    const int bn0 = blockIdx.x * 64;

    float acc[8][4];
#pragma unroll
    for (int i = 0; i < 8; i++)
#pragma unroll
        for (int j = 0; j < 4; j++) acc[i][j] = 0.f;

    for (int k0 = 0; k0 < 512; k0 += 16) {
        // A tile: 128x16 = 512 float4, 2 per thread, stored transposed
#pragma unroll
        for (int r = 0; r < 2; r++) {
            int f = tid * 2 + r;          // 0..511
            int row = f >> 2;             // 0..127
            int seg = f & 3;              // 0..3
            float4 v = *(const float4*)&A[(bm0 + row) * 512 + k0 + seg * 4];
            As[seg*4+0][row] = v.x; As[seg*4+1][row] = v.y;
            As[seg*4+2][row] = v.z; As[seg*4+3][row] = v.w;
        }
        // B tile: 16x64 = 256 float4, 1 per thread
        *(float4*)&Bs[ty][tx*4] = *(const float4*)&Bm[(k0 + ty) * 512 + bn0 + tx*4];
        __syncthreads();

#pragma unroll
        for (int kk = 0; kk < 16; kk++) {
            float4 a0 = *(const float4*)&As[kk][ty*8];
            float4 a1 = *(const float4*)&As[kk][ty*8+4];
            float4 b4 = *(const float4*)&Bs[kk][tx*4];
            float a[8] = {a0.x,a0.y,a0.z,a0.w,a1.x,a1.y,a1.z,a1.w};
            float bj[4] = {b4.x,b4.y,b4.z,b4.w};
#pragma unroll
            for (int i = 0; i < 8; i++)
#pragma unroll
                for (int j = 0; j < 4; j++) acc[i][j] += a[i] * bj[j];
        }
        __syncthreads();
    }

#pragma unroll
    for (int i = 0; i < 8; i++) {
        int row = bm0 + ty*8 + i;
        int col = bn0 + tx*4;
        float4 o;
        o.x = acc[i][0]*scale + bias[col+0];
        o.y = acc[i][1]*scale + bias[col+1];
        o.z = acc[i][2]*scale + bias[col+2];
        o.w = acc[i][3]*scale + bias[col+3];
        if (resid) {
            float4 r4 = *(const float4*)&resid[row*512 + col];
            o.x += r4.x; o.y += r4.y; o.z += r4.z; o.w += r4.w;
        }
        *(float4*)&C[row*512 + col] = o;
    }
}

__global__ __launch_bounds__(256) void qkv_gemm(const float* __restrict__ x,
    const float* __restrict__ Wq, const float* __restrict__ bq,
    const float* __restrict__ Wk, const float* __restrict__ bk,
    const float* __restrict__ Wv, const float* __restrict__ bv)
{
    const float* W; const float* bias; float* C;
    if (blockIdx.z == 0)      { W = Wq; bias = bq; C = g_q; }
    else if (blockIdx.z == 1) { W = Wk; bias = bk; C = g_k; }
    else                      { W = Wv; bias = bv; C = g_v; }
    sgemm_tile(x, W, C, bias, nullptr, 1.0f);
}

__global__ __launch_bounds__(256) void out_gemm(const float* __restrict__ Wo,
                                                const float* __restrict__ bo,
                                                const float* __restrict__ x)
{
    // res = x + (sum_c ctx)/NVAR @ Wo + bo
    sgemm_tile(g_ctx, Wo, g_res, bo, x, 1.0f / (float)NVAR);
}

// ---------------------------------------------------------------------------
// Flash attention over 4 key-variables, accumulating the sum over c.
// Block = 128 threads handles one (q,b,h, 64-row Q tile).
// smem: qs[64][68] (k-major Q), kp[64][68] (k-major K, reused as s-major P),
//       vs[64][64].
// ---------------------------------------------------------------------------
#define QS_STRIDE 68
__global__ __launch_bounds__(128) void attn_kernel()
{
    extern __shared__ float sm[];
    float* qs = sm;                 // 64*68
    float* kp = sm + 64*QS_STRIDE;  // 64*68 (K tile then P tile)
    float* vs = kp + 64*QS_STRIDE;  // 64*64

    const int tid = threadIdx.x;
    const int tc = tid & 15;  // column group (x4)
    const int tr = tid >> 4;  // row group (x8)
    const int t0 = blockIdx.x * 64;
    const int h  = blockIdx.y;
    const int qb = blockIdx.z;       // q*BB + b
    const int b  = qb & (BB - 1);

    const int baseQ = (qb*TT + t0) * 512 + h*64;
    // Load Q tile transposed (k-major), folding in 1/sqrt(DK)=0.125
#pragma unroll
    for (int u = 0; u < 8; u++) {
        int f = tid + 128*u;         // 0..1023
        int m = f >> 4;              // 0..63
        int seg = f & 15;            // float4 within row
        float4 v = *(const float4*)&g_q[baseQ + m*512 + seg*4];
        qs[(seg*4+0)*QS_STRIDE + m] = v.x * 0.125f;
        qs[(seg*4+1)*QS_STRIDE + m] = v.y * 0.125f;
        qs[(seg*4+2)*QS_STRIDE + m] = v.z * 0.125f;
        qs[(seg*4+3)*QS_STRIDE + m] = v.w * 0.125f;
    }

    float acc[8][4], o[8][4], mrow[8], lrow[8];
#pragma unroll
    for (int i = 0; i < 8; i++) {
        mrow[i] = -1e30f; lrow[i] = 0.f;
#pragma unroll
        for (int j = 0; j < 4; j++) { acc[i][j] = 0.f; o[i][j] = 0.f; }
    }

    for (int c = 0; c < NVAR; c++) {
        const int baseKV = (c*BB + b) * TT * 512 + h*64;
        for (int s0 = 0; s0 < TT; s0 += 64) {
            // Load K (transposed, k-major) and V (direct)
#pragma unroll
            for (int u = 0; u < 8; u++) {
                int f = tid + 128*u;
                int n = f >> 4; int seg = f & 15;
                int gi = baseKV + (s0 + n)*512 + seg*4;
                float4 kv = *(const float4*)&g_k[gi];
                kp[(seg*4+0)*QS_STRIDE + n] = kv.x;
                kp[(seg*4+1)*QS_STRIDE + n] = kv.y;
                kp[(seg*4+2)*QS_STRIDE + n] = kv.z;
                kp[(seg*4+3)*QS_STRIDE + n] = kv.w;
                *(float4*)&vs[n*64 + seg*4] = *(const float4*)&g_v[gi];
            }
            __syncthreads();

            // S = (Q*scale) @ K^T   (64x64, micro 8x4)
            float sfr[8][4];
#pragma unroll
            for (int i = 0; i < 8; i++)
#pragma unroll
                for (int j = 0; j < 4; j++) sfr[i][j] = 0.f;
#pragma unroll 8
            for (int kk = 0; kk < 64; kk++) {
                float4 a0 = *(const float4*)&qs[kk*QS_STRIDE + tr*8];
                float4 a1 = *(const float4*)&qs[kk*QS_STRIDE + tr*8 + 4];
                float4 b4 = *(const float4*)&kp[kk*QS_STRIDE + tc*4];
                float a[8] = {a0.x,a0.y,a0.z,a0.w,a1.x,a1.y,a1.z,a1.w};
                float bj[4] = {b4.x,b4.y,b4.z,b4.w};
#pragma unroll
                for (int i = 0; i < 8; i++)
#pragma unroll
                    for (int j = 0; j < 4; j++) sfr[i][j] += a[i]*bj[j];
            }
            __syncthreads();  // all K reads done before kp is reused for P

            // Online softmax (row owned by 16 lanes; xor-shuffle width 16)
#pragma unroll
            for (int i = 0; i < 8; i++) {
                float mx = fmaxf(fmaxf(sfr[i][0], sfr[i][1]),
                                 fmaxf(sfr[i][2], sfr[i][3]));
#pragma unroll
                for (int off = 1; off < 16; off <<= 1)
                    mx = fmaxf(mx, __shfl_xor_sync(0xffffffffu, mx, off));
                float mnew = fmaxf(mrow[i], mx);
                float corr = __expf(mrow[i] - mnew);
                float rs = 0.f;
#pragma unroll
                for (int j = 0; j < 4; j++) {
                    float p = __expf(sfr[i][j] - mnew);
                    sfr[i][j] = p; rs += p;
                }
#pragma unroll
                for (int off = 1; off < 16; off <<= 1)
                    rs += __shfl_xor_sync(0xffffffffu, rs, off);
                lrow[i] = lrow[i]*corr + rs;
                mrow[i] = mnew;
#pragma unroll
                for (int j = 0; j < 4; j++) o[i][j] *= corr;
                // store P transposed: Ps[s][m]
#pragma unroll
                for (int j = 0; j < 4; j++)
                    kp[(tc*4 + j)*QS_STRIDE + tr*8 + i] = sfr[i][j];
            }
            __syncthreads();

            // O += P @ V
#pragma unroll 8
            for (int ss = 0; ss < 64; ss++) {
                float4 p0 = *(const float4*)&kp[ss*QS_STRIDE + tr*8];
                float4 p1 = *(const float4*)&kp[ss*QS_STRIDE + tr*8 + 4];
                float4 vv = *(const float4*)&vs[ss*64 + tc*4];
                float pa[8] = {p0.x,p0.y,p0.z,p0.w,p1.x,p1.y,p1.z,p1.w};
                float vj[4] = {vv.x,vv.y,vv.z,vv.w};
#pragma unroll
                for (int i = 0; i < 8; i++)
#pragma unroll
                    for (int j = 0; j < 4; j++) o[i][j] += pa[i]*vj[j];
            }
            __syncthreads();  // before next tile overwrites kp/vs
        }
        // fold this key-variable into the accumulator
#pragma unroll
        for (int i = 0; i < 8; i++) {
            float invl = 1.f / lrow[i];
#pragma unroll
            for (int j = 0; j < 4; j++) { acc[i][j] += o[i][j]*invl; o[i][j] = 0.f; }
            mrow[i] = -1e30f; lrow[i] = 0.f;
        }
    }

    // write ctx_sum: [qb, t, h*64+dv]
    const int baseO = (qb*TT + t0) * 512 + h*64;
#pragma unroll
    for (int i = 0; i < 8; i++) {
        float4 w4 = make_float4(acc[i][0], acc[i][1], acc[i][2], acc[i][3]);
        *(float4*)&g_ctx[baseO + (tr*8 + i)*512 + tc*4] = w4;
    }
}

// ---------------------------------------------------------------------------
// LayerNorm: one block per row of 512
// ---------------------------------------------------------------------------
__global__ __launch_bounds__(128) void ln_kernel(const float* __restrict__ gamma,
                                                 const float* __restrict__ beta,
                                                 float* __restrict__ out)
{
    const int row = blockIdx.x;
    const int t = threadIdx.x;
    float4 v = *(const float4*)&g_res[row*512 + t*4];
    float s  = v.x + v.y + v.z + v.w;
    float ss = v.x*v.x + v.y*v.y + v.z*v.z + v.w*v.w;
#pragma unroll
    for (int off = 16; off; off >>= 1) {
        s  += __shfl_xor_sync(0xffffffffu, s, off);
        ss += __shfl_xor_sync(0xffffffffu, ss, off);
    }
    __shared__ float as[4], ass[4];
    if ((t & 31) == 0) { as[t >> 5] = s; ass[t >> 5] = ss; }
    __syncthreads();
    s  = as[0] + as[1] + as[2] + as[3];
    ss = ass[0] + ass[1] + ass[2] + ass[3];
    float mu  = s * (1.f / 512.f);
    float var = ss * (1.f / 512.f) - mu * mu;
    float inv = rsqrtf(var + 1e-5f);
    float4 g = *(const float4*)&gamma[t*4];
    float4 bb = *(const float4*)&beta[t*4];
    float4 o4;
    o4.x = (v.x - mu)*inv*g.x + bb.x;
    o4.y = (v.y - mu)*inv*g.y + bb.y;
    o4.z = (v.z - mu)*inv*g.z + bb.z;
    o4.w = (v.w - mu)*inv*g.w + bb.w;
    *(float4*)&out[row*512 + t*4] = o4;
}

extern "C" void kernel_launch(void* const* d_in, const int* in_sizes, int n_in,
                              void* d_out, int out_size)
{
    const float* x     = (const float*)d_in[0];
    const float* Wq    = (const float*)d_in[1];
    const float* bq    = (const float*)d_in[2];
    const float* Wk    = (const float*)d_in[3];
    const float* bk    = (const float*)d_in[4];
    const float* Wv    = (const float*)d_in[5];
    const float* bv    = (const float*)d_in[6];
    const float* Wo    = (const float*)d_in[7];
    const float* bo    = (const float*)d_in[8];
    const float* gamma = (const float*)d_in[9];
    const float* beta  = (const float*)d_in[10];
    float* out = (float*)d_out;

    const int attn_smem = (64*QS_STRIDE*2 + 64*64) * (int)sizeof(float);  // 51200
    cudaFuncSetAttribute(attn_kernel, cudaFuncAttributeMaxDynamicSharedMemorySize,
                         attn_smem);

    qkv_gemm<<<dim3(512/64, MROWS/128, 3), 256>>>(x, Wq, bq, Wk, bk, Wv, bv);
    attn_kernel<<<dim3(TT/64, HH, NVAR*BB), 128, attn_smem>>>();
    out_gemm<<<dim3(512/64, MROWS/128, 1), 256>>>(Wo, bo, x);
    ln_kernel<<<MROWS, 128>>>(gamma, beta, out);
}

// round 3
// speedup vs baseline: 1.0919x; 1.0919x over previous
#include <cuda_runtime.h>
#include <math.h>

#define NVAR 4
#define BB   4
#define TT   512
#define DD   512
#define HH   8
#define MROWS (NVAR*BB*TT)   // 8192

// Scratch (alloc-free rule: __device__ globals)
__device__ float g_q[MROWS*DD];
__device__ float g_k[MROWS*DD];
__device__ float g_v[MROWS*DD];
__device__ float g_ctx[MROWS*DD];
__device__ float g_res[MROWS*DD];

// ------------------------- packed f32x2 helpers ----------------------------
typedef unsigned long long u64;

__device__ __forceinline__ u64 pack2(float lo, float hi) {
    u64 r;
    asm("mov.b64 %0, {%1, %2};" : "=l"(r) : "f"(lo), "f"(hi));
    return r;
}
__device__ __forceinline__ u64 dup2(float v) {
    u64 r;
    asm("mov.b64 %0, {%1, %1};" : "=l"(r) : "f"(v));
    return r;
}
__device__ __forceinline__ void unpk2(u64 p, float& lo, float& hi) {
    asm("mov.b64 {%0, %1}, %2;" : "=f"(lo), "=f"(hi) : "l"(p));
}
__device__ __forceinline__ u64 fma2(u64 a, u64 b, u64 c) {
    u64 d;
    asm("fma.rn.f32x2 %0, %1, %2, %3;" : "=l"(d) : "l"(a), "l"(b), "l"(c));
    return d;
}
__device__ __forceinline__ u64 mul2(u64 a, u64 b) {
    u64 d;
    asm("mul.rn.f32x2 %0, %1, %2;" : "=l"(d) : "l"(a), "l"(b));
    return d;
}

// ---------------------------------------------------------------------------
// Tiled SGEMM body: C[128x64 tile] = scale*(A@B) + bias (+ resid)
// A: [M,512] row-major, B: [512,512] row-major, C: [M,512]
// 256 threads, BM=128, BN=64, BK=16, micro-tile 8x4 (rows paired as f32x2).
// ---------------------------------------------------------------------------
__device__ __forceinline__ void sgemm_tile(const float* __restrict__ A,
                                           const float* __restrict__ Bm,
                                           float* __restrict__ C,
                                           const float* __restrict__ bias,
                                           const float* __restrict__ resid,
                                           float scale)
{
    __shared__ float As[16][132];  // [k][m], padded (row = 528B, 16B aligned)
    __shared__ float Bs[16][68];   // [k][n], padded (row = 272B, 16B aligned)

    const int tid = threadIdx.x;
    const int tx = tid & 15;   // n direction (x4)
    const int ty = tid >> 4;   // m direction (x8)
    const int bm0 = blockIdx.y * 128;
    const int bn0 = blockIdx.x * 64;

    u64 acc2[4][4];            // [row-pair][col], each u64 = rows (2ip, 2ip+1)
#pragma unroll
    for (int i = 0; i < 4; i++)
#pragma unroll
        for (int j = 0; j < 4; j++) acc2[i][j] = 0ull;

    for (int k0 = 0; k0 < 512; k0 += 16) {
        // A tile: 128x16 = 512 float4, 2 per thread, stored transposed
#pragma unroll
        for (int r = 0; r < 2; r++) {
            int f = tid * 2 + r;          // 0..511
            int row = f >> 2;             // 0..127
            int seg = f & 3;              // 0..3
            float4 v = *(const float4*)&A[(bm0 + row) * 512 + k0 + seg * 4];
            As[seg*4+0][row] = v.x; As[seg*4+1][row] = v.y;
            As[seg*4+2][row] = v.z; As[seg*4+3][row] = v.w;
        }
        // B tile: 16x64 = 256 float4, 1 per thread
        *(float4*)&Bs[ty][tx*4] = *(const float4*)&Bm[(k0 + ty) * 512 + bn0 + tx*4];
        __syncthreads();

#pragma unroll
        for (int kk = 0; kk < 16; kk++) {
            ulonglong2 aA = *(const ulonglong2*)&As[kk][ty*8];     // pairs (0,1),(2,3)
            ulonglong2 aB = *(const ulonglong2*)&As[kk][ty*8+4];   // pairs (4,5),(6,7)
            float4 b4 = *(const float4*)&Bs[kk][tx*4];
            u64 ap[4] = {aA.x, aA.y, aB.x, aB.y};
            u64 bd[4] = {dup2(b4.x), dup2(b4.y), dup2(b4.z), dup2(b4.w)};
#pragma unroll
            for (int i = 0; i < 4; i++)
#pragma unroll
                for (int j = 0; j < 4; j++)
                    acc2[i][j] = fma2(ap[i], bd[j], acc2[i][j]);
        }
        __syncthreads();
    }

    // unpack and write
#pragma unroll
    for (int ip = 0; ip < 4; ip++) {
        float r0[4], r1[4];
#pragma unroll
        for (int j = 0; j < 4; j++) unpk2(acc2[ip][j], r0[j], r1[j]);
#pragma unroll
        for (int h = 0; h < 2; h++) {
            const float* rr = h ? r1 : r0;
            int row = bm0 + ty*8 + ip*2 + h;
            int col = bn0 + tx*4;
            float4 o;
            o.x = rr[0]*scale + bias[col+0];
            o.y = rr[1]*scale + bias[col+1];
            o.z = rr[2]*scale + bias[col+2];
            o.w = rr[3]*scale + bias[col+3];
            if (resid) {
                float4 q4 = *(const float4*)&resid[row*512 + col];
                o.x += q4.x; o.y += q4.y; o.z += q4.z; o.w += q4.w;
            }
            *(float4*)&C[row*512 + col] = o;
        }
    }
}

__global__ __launch_bounds__(256) void qkv_gemm(const float* __restrict__ x,
    const float* __restrict__ Wq, const float* __restrict__ bq,
    const float* __restrict__ Wk, const float* __restrict__ bk,
    const float* __restrict__ Wv, const float* __restrict__ bv)
{
    const float* W; const float* bias; float* C;
    if (blockIdx.z == 0)      { W = Wq; bias = bq; C = g_q; }
    else if (blockIdx.z == 1) { W = Wk; bias = bk; C = g_k; }
    else                      { W = Wv; bias = bv; C = g_v; }
    sgemm_tile(x, W, C, bias, nullptr, 1.0f);
}

__global__ __launch_bounds__(256) void out_gemm(const float* __restrict__ Wo,
                                                const float* __restrict__ bo,
                                                const float* __restrict__ x)
{
    // res = x + (sum_c ctx)/NVAR @ Wo + bo
    sgemm_tile(g_ctx, Wo, g_res, bo, x, 1.0f / (float)NVAR);
}

// ---------------------------------------------------------------------------
// Flash attention over 4 key-variables, accumulating the sum over c.
// Block = 128 threads handles one (q,b,h, 64-row Q tile).
// smem: qs[64][68] (k-major Q), kp[64][68] (k-major K, reused as s-major P),
//       vs[64][64].  Row-pairs packed as f32x2 in all matmul loops.
// ---------------------------------------------------------------------------
#define QS_STRIDE 68
__global__ __launch_bounds__(128) void attn_kernel()
{
    extern __shared__ float sm[];
    float* qs = sm;                 // 64*68
    float* kp = sm + 64*QS_STRIDE;  // 64*68 (K tile then P tile)
    float* vs = kp + 64*QS_STRIDE;  // 64*64

    const int tid = threadIdx.x;
    const int tc = tid & 15;  // column group (x4)
    const int tr = tid >> 4;  // row group (x8)
    const int t0 = blockIdx.x * 64;
    const int h  = blockIdx.y;
    const int qb = blockIdx.z;       // q*BB + b
    const int b  = qb & (BB - 1);

    const int baseQ = (qb*TT + t0) * 512 + h*64;
    // Load Q tile transposed (k-major), folding in 1/sqrt(DK)=0.125
#pragma unroll
    for (int u = 0; u < 8; u++) {
        int f = tid + 128*u;         // 0..1023
        int m = f >> 4;              // 0..63
        int seg = f & 15;            // float4 within row
        float4 v = *(const float4*)&g_q[baseQ + m*512 + seg*4];
        qs[(seg*4+0)*QS_STRIDE + m] = v.x * 0.125f;
        qs[(seg*4+1)*QS_STRIDE + m] = v.y * 0.125f;
        qs[(seg*4+2)*QS_STRIDE + m] = v.z * 0.125f;
        qs[(seg*4+3)*QS_STRIDE + m] = v.w * 0.125f;
    }

    u64 acc2[4][4], o2[4][4];
    float mrow[8], lrow[8];
#pragma unroll
    for (int i = 0; i < 4; i++)
#pragma unroll
        for (int j = 0; j < 4; j++) { acc2[i][j] = 0ull; o2[i][j] = 0ull; }
#pragma unroll
    for (int i = 0; i < 8; i++) { mrow[i] = -1e30f; lrow[i] = 0.f; }

    for (int c = 0; c < NVAR; c++) {
        const int baseKV = (c*BB + b) * TT * 512 + h*64;
        for (int s0 = 0; s0 < TT; s0 += 64) {
            // Load K (transposed, k-major) and V (direct)
#pragma unroll
            for (int u = 0; u < 8; u++) {
                int f = tid + 128*u;
                int n = f >> 4; int seg = f & 15;
                int gi = baseKV + (s0 + n)*512 + seg*4;
                float4 kv = *(const float4*)&g_k[gi];
                kp[(seg*4+0)*QS_STRIDE + n] = kv.x;
                kp[(seg*4+1)*QS_STRIDE + n] = kv.y;
                kp[(seg*4+2)*QS_STRIDE + n] = kv.z;
                kp[(seg*4+3)*QS_STRIDE + n] = kv.w;
                *(float4*)&vs[n*64 + seg*4] = *(const float4*)&g_v[gi];
            }
            __syncthreads();

            // S = (Q*scale) @ K^T   (64x64, row-pairs packed)
            u64 s2[4][4];
#pragma unroll
            for (int i = 0; i < 4; i++)
#pragma unroll
                for (int j = 0; j < 4; j++) s2[i][j] = 0ull;
#pragma unroll 8
            for (int kk = 0; kk < 64; kk++) {
                ulonglong2 aA = *(const ulonglong2*)&qs[kk*QS_STRIDE + tr*8];
                ulonglong2 aB = *(const ulonglong2*)&qs[kk*QS_STRIDE + tr*8 + 4];
                float4 b4 = *(const float4*)&kp[kk*QS_STRIDE + tc*4];
                u64 ap[4] = {aA.x, aA.y, aB.x, aB.y};
                u64 bd[4] = {dup2(b4.x), dup2(b4.y), dup2(b4.z), dup2(b4.w)};
#pragma unroll
                for (int i = 0; i < 4; i++)
#pragma unroll
                    for (int j = 0; j < 4; j++)
                        s2[i][j] = fma2(ap[i], bd[j], s2[i][j]);
            }
            __syncthreads();  // all K reads done before kp is reused for P

            // unpack S into per-row scalars
            float sfr[8][4];
#pragma unroll
            for (int ip = 0; ip < 4; ip++)
#pragma unroll
                for (int j = 0; j < 4; j++)
                    unpk2(s2[ip][j], sfr[2*ip][j], sfr[2*ip+1][j]);

            // Online softmax (row owned by 16 lanes; xor-shuffle width 16)
            float corrv[8];
#pragma unroll
            for (int i = 0; i < 8; i++) {
                float mx = fmaxf(fmaxf(sfr[i][0], sfr[i][1]),
                                 fmaxf(sfr[i][2], sfr[i][3]));
#pragma unroll
                for (int off = 1; off < 16; off <<= 1)
                    mx = fmaxf(mx, __shfl_xor_sync(0xffffffffu, mx, off));
                float mnew = fmaxf(mrow[i], mx);
                float corr = __expf(mrow[i] - mnew);
                float rs = 0.f;
#pragma unroll
                for (int j = 0; j < 4; j++) {
                    float p = __expf(sfr[i][j] - mnew);
                    sfr[i][j] = p; rs += p;
                }
#pragma unroll
                for (int off = 1; off < 16; off <<= 1)
                    rs += __shfl_xor_sync(0xffffffffu, rs, off);
                lrow[i] = lrow[i]*corr + rs;
                mrow[i] = mnew;
                corrv[i] = corr;
                // store P transposed: Ps[s][m]
#pragma unroll
                for (int j = 0; j < 4; j++)
                    kp[(tc*4 + j)*QS_STRIDE + tr*8 + i] = sfr[i][j];
            }
            // rescale O accumulator (packed row-pairs)
#pragma unroll
            for (int ip = 0; ip < 4; ip++) {
                u64 c2 = pack2(corrv[2*ip], corrv[2*ip+1]);
#pragma unroll
                for (int j = 0; j < 4; j++) o2[ip][j] = mul2(o2[ip][j], c2);
            }
            __syncthreads();

            // O += P @ V  (row-pairs packed)
#pragma unroll 8
            for (int ss = 0; ss < 64; ss++) {
                ulonglong2 pA = *(const ulonglong2*)&kp[ss*QS_STRIDE + tr*8];
                ulonglong2 pB = *(const ulonglong2*)&kp[ss*QS_STRIDE + tr*8 + 4];
                float4 vv = *(const float4*)&vs[ss*64 + tc*4];
                u64 pp[4] = {pA.x, pA.y, pB.x, pB.y};
                u64 vd[4] = {dup2(vv.x), dup2(vv.y), dup2(vv.z), dup2(vv.w)};
#pragma unroll
                for (int i = 0; i < 4; i++)
#pragma unroll
                    for (int j = 0; j < 4; j++)
                        o2[i][j] = fma2(pp[i], vd[j], o2[i][j]);
            }
            __syncthreads();  // before next tile overwrites kp/vs
        }
        // fold this key-variable into the accumulator
#pragma unroll
        for (int ip = 0; ip < 4; ip++) {
            u64 il2 = pack2(1.f / lrow[2*ip], 1.f / lrow[2*ip+1]);
#pragma unroll
            for (int j = 0; j < 4; j++) {
                acc2[ip][j] = fma2(o2[ip][j], il2, acc2[ip][j]);
                o2[ip][j] = 0ull;
            }
        }
#pragma unroll
        for (int i = 0; i < 8; i++) { mrow[i] = -1e30f; lrow[i] = 0.f; }
    }

    // write ctx_sum: [qb, t, h*64+dv]
    const int baseO = (qb*TT + t0) * 512 + h*64;
#pragma unroll
    for (int ip = 0; ip < 4; ip++) {
        float r0[4], r1[4];
#pragma unroll
        for (int j = 0; j < 4; j++) unpk2(acc2[ip][j], r0[j], r1[j]);
        *(float4*)&g_ctx[baseO + (tr*8 + 2*ip+0)*512 + tc*4] =
            make_float4(r0[0], r0[1], r0[2], r0[3]);
        *(float4*)&g_ctx[baseO + (tr*8 + 2*ip+1)*512 + tc*4] =
            make_float4(r1[0], r1[1], r1[2], r1[3]);
    }
}

// ---------------------------------------------------------------------------
// LayerNorm: one block per row of 512
// ---------------------------------------------------------------------------
__global__ __launch_bounds__(128) void ln_kernel(const float* __restrict__ gamma,
                                                 const float* __restrict__ beta,
                                                 float* __restrict__ out)
{
    const int row = blockIdx.x;
    const int t = threadIdx.x;
    float4 v = *(const float4*)&g_res[row*512 + t*4];
    float s  = v.x + v.y + v.z + v.w;
    float ss = v.x*v.x + v.y*v.y + v.z*v.z + v.w*v.w;
#pragma unroll
    for (int off = 16; off; off >>= 1) {
        s  += __shfl_xor_sync(0xffffffffu, s, off);
        ss += __shfl_xor_sync(0xffffffffu, ss, off);
    }
    __shared__ float as[4], ass[4];
    if ((t & 31) == 0) { as[t >> 5] = s; ass[t >> 5] = ss; }
    __syncthreads();
    s  = as[0] + as[1] + as[2] + as[3];
    ss = ass[0] + ass[1] + ass[2] + ass[3];
    float mu  = s * (1.f / 512.f);
    float var = ss * (1.f / 512.f) - mu * mu;
    float inv = rsqrtf(var + 1e-5f);
    float4 g = *(const float4*)&gamma[t*4];
    float4 bb = *(const float4*)&beta[t*4];
    float4 o4;
    o4.x = (v.x - mu)*inv*g.x + bb.x;
    o4.y = (v.y - mu)*inv*g.y + bb.y;
    o4.z = (v.z - mu)*inv*g.z + bb.z;
    o4.w = (v.w - mu)*inv*g.w + bb.w;
    *(float4*)&out[row*512 + t*4] = o4;
}

extern "C" void kernel_launch(void* const* d_in, const int* in_sizes, int n_in,
                              void* d_out, int out_size)
{
    const float* x     = (const float*)d_in[0];
    const float* Wq    = (const float*)d_in[1];
    const float* bq    = (const float*)d_in[2];
    const float* Wk    = (const float*)d_in[3];
    const float* bk    = (const float*)d_in[4];
    const float* Wv    = (const float*)d_in[5];
    const float* bv    = (const float*)d_in[6];
    const float* Wo    = (const float*)d_in[7];
    const float* bo    = (const float*)d_in[8];
    const float* gamma = (const float*)d_in[9];
    const float* beta  = (const float*)d_in[10];
    float* out = (float*)d_out;

    const int attn_smem = (64*QS_STRIDE*2 + 64*64) * (int)sizeof(float);  // 51200
    cudaFuncSetAttribute(attn_kernel, cudaFuncAttributeMaxDynamicSharedMemorySize,
                         attn_smem);

    qkv_gemm<<<dim3(512/64, MROWS/128, 3), 256>>>(x, Wq, bq, Wk, bk, Wv, bv);
    attn_kernel<<<dim3(TT/64, HH, NVAR*BB), 128, attn_smem>>>();
    out_gemm<<<dim3(512/64, MROWS/128, 1), 256>>>(Wo, bo, x);
    ln_kernel<<<MROWS, 128>>>(gamma, beta, out);
}

// round 4
// speedup vs baseline: 1.1746x; 1.0758x over previous
#include <cuda_runtime.h>
#include <math.h>

#define NVAR 4
#define BB   4
#define TT   512
#define DD   512
#define HH   8
#define MROWS (NVAR*BB*TT)   // 8192

// Scratch (alloc-free rule: __device__ globals)
__device__ float g_q[MROWS*DD];
__device__ float g_k[MROWS*DD];
__device__ float g_v[MROWS*DD];
__device__ float g_ctx[MROWS*DD];
__device__ float g_res[MROWS*DD];

// ------------------------- packed f32x2 helpers ----------------------------
typedef unsigned long long u64;

__device__ __forceinline__ u64 pack2(float lo, float hi) {
    u64 r;
    asm("mov.b64 %0, {%1, %2};" : "=l"(r) : "f"(lo), "f"(hi));
    return r;
}
__device__ __forceinline__ u64 dup2(float v) {
    u64 r;
    asm("mov.b64 %0, {%1, %1};" : "=l"(r) : "f"(v));
    return r;
}
__device__ __forceinline__ void unpk2(u64 p, float& lo, float& hi) {
    asm("mov.b64 {%0, %1}, %2;" : "=f"(lo), "=f"(hi) : "l"(p));
}
__device__ __forceinline__ u64 fma2(u64 a, u64 b, u64 c) {
    u64 d;
    asm("fma.rn.f32x2 %0, %1, %2, %3;" : "=l"(d) : "l"(a), "l"(b), "l"(c));
    return d;
}
__device__ __forceinline__ u64 mul2(u64 a, u64 b) {
    u64 d;
    asm("mul.rn.f32x2 %0, %1, %2;" : "=l"(d) : "l"(a), "l"(b));
    return d;
}

// ---------------------------------------------------------------------------
// Tiled SGEMM body: C[128x64 tile] = scale*(A@B) + bias (+ resid)
// Software-pipelined: next A/B fragments staged in registers during compute.
// 256 threads, BM=128, BN=64, BK=16, micro-tile 8x4 (rows paired as f32x2).
// ---------------------------------------------------------------------------
__device__ __forceinline__ void sgemm_tile(const float* __restrict__ A,
                                           const float* __restrict__ Bm,
                                           float* __restrict__ C,
                                           const float* __restrict__ bias,
                                           const float* __restrict__ resid,
                                           float scale)
{
    __shared__ float As[16][132];  // [k][m], padded
    __shared__ float Bs[16][68];   // [k][n], padded

    const int tid = threadIdx.x;
    const int tx = tid & 15;   // n direction (x4)
    const int ty = tid >> 4;   // m direction (x8)
    const int bm0 = blockIdx.y * 128;
    const int bn0 = blockIdx.x * 64;

    // fixed per-thread load coordinates
    const int lrow0 = (tid * 2) >> 2;          // A row for r=0
    const int lseg0 = (tid * 2) & 3;
    const int lrow1 = (tid * 2 + 1) >> 2;
    const int lseg1 = (tid * 2 + 1) & 3;

    u64 acc2[4][4];
#pragma unroll
    for (int i = 0; i < 4; i++)
#pragma unroll
        for (int j = 0; j < 4; j++) acc2[i][j] = 0ull;

    // prologue: stage k0 = 0
    float4 aReg0 = *(const float4*)&A[(bm0 + lrow0) * 512 + 0 + lseg0 * 4];
    float4 aReg1 = *(const float4*)&A[(bm0 + lrow1) * 512 + 0 + lseg1 * 4];
    float4 bReg  = *(const float4*)&Bm[(0 + ty) * 512 + bn0 + tx*4];

    for (int k0 = 0; k0 < 512; k0 += 16) {
        // commit staged fragments to smem
        As[lseg0*4+0][lrow0] = aReg0.x; As[lseg0*4+1][lrow0] = aReg0.y;
        As[lseg0*4+2][lrow0] = aReg0.z; As[lseg0*4+3][lrow0] = aReg0.w;
        As[lseg1*4+0][lrow1] = aReg1.x; As[lseg1*4+1][lrow1] = aReg1.y;
        As[lseg1*4+2][lrow1] = aReg1.z; As[lseg1*4+3][lrow1] = aReg1.w;
        *(float4*)&Bs[ty][tx*4] = bReg;
        __syncthreads();

        // stage k0+16 while computing k0
        if (k0 + 16 < 512) {
            aReg0 = *(const float4*)&A[(bm0 + lrow0) * 512 + (k0+16) + lseg0 * 4];
            aReg1 = *(const float4*)&A[(bm0 + lrow1) * 512 + (k0+16) + lseg1 * 4];
            bReg  = *(const float4*)&Bm[(k0+16 + ty) * 512 + bn0 + tx*4];
        }

#pragma unroll
        for (int kk = 0; kk < 16; kk++) {
            ulonglong2 aA = *(const ulonglong2*)&As[kk][ty*8];
            ulonglong2 aB = *(const ulonglong2*)&As[kk][ty*8+4];
            float4 b4 = *(const float4*)&Bs[kk][tx*4];
            u64 ap[4] = {aA.x, aA.y, aB.x, aB.y};
            u64 bd[4] = {dup2(b4.x), dup2(b4.y), dup2(b4.z), dup2(b4.w)};
#pragma unroll
            for (int i = 0; i < 4; i++)
#pragma unroll
                for (int j = 0; j < 4; j++)
                    acc2[i][j] = fma2(ap[i], bd[j], acc2[i][j]);
        }
        __syncthreads();
    }

    // unpack and write
#pragma unroll
    for (int ip = 0; ip < 4; ip++) {
        float r0[4], r1[4];
#pragma unroll
        for (int j = 0; j < 4; j++) unpk2(acc2[ip][j], r0[j], r1[j]);
#pragma unroll
        for (int h = 0; h < 2; h++) {
            const float* rr = h ? r1 : r0;
            int row = bm0 + ty*8 + ip*2 + h;
            int col = bn0 + tx*4;
            float4 o;
            o.x = rr[0]*scale + bias[col+0];
            o.y = rr[1]*scale + bias[col+1];
            o.z = rr[2]*scale + bias[col+2];
            o.w = rr[3]*scale + bias[col+3];
            if (resid) {
                float4 q4 = *(const float4*)&resid[row*512 + col];
                o.x += q4.x; o.y += q4.y; o.z += q4.z; o.w += q4.w;
            }
            *(float4*)&C[row*512 + col] = o;
        }
    }
}

__global__ __launch_bounds__(256) void qkv_gemm(const float* __restrict__ x,
    const float* __restrict__ Wq, const float* __restrict__ bq,
    const float* __restrict__ Wk, const float* __restrict__ bk,
    const float* __restrict__ Wv, const float* __restrict__ bv)
{
    const float* W; const float* bias; float* C;
    if (blockIdx.z == 0)      { W = Wq; bias = bq; C = g_q; }
    else if (blockIdx.z == 1) { W = Wk; bias = bk; C = g_k; }
    else                      { W = Wv; bias = bv; C = g_v; }
    sgemm_tile(x, W, C, bias, nullptr, 1.0f);
}

__global__ __launch_bounds__(256) void out_gemm(const float* __restrict__ Wo,
                                                const float* __restrict__ bo,
                                                const float* __restrict__ x)
{
    // res = x + (sum_c ctx)/NVAR @ Wo + bo
    sgemm_tile(g_ctx, Wo, g_res, bo, x, 1.0f / (float)NVAR);
}

// ---------------------------------------------------------------------------
// Flash attention over 4 key-variables, accumulating the sum over c.
// Block = 128 threads handles one (q,b,h, 64-row Q tile).
// smem: qs[64][68] (k-major Q), kp[64][68] (k-major K, reused as s-major P),
//       vs[64][64].  Row-pairs packed as f32x2 in all matmul loops.
// P store is vectorized: 8 conflict-free STS.128 per thread (was 32 scalar
// stores at 8-way bank conflict).
// ---------------------------------------------------------------------------
#define QS_STRIDE 68
__global__ __launch_bounds__(128) void attn_kernel()
{
    extern __shared__ float sm[];
    float* qs = sm;                 // 64*68
    float* kp = sm + 64*QS_STRIDE;  // 64*68 (K tile then P tile)
    float* vs = kp + 64*QS_STRIDE;  // 64*64

    const int tid = threadIdx.x;
    const int tc = tid & 15;  // column group (x4)
    const int tr = tid >> 4;  // row group (x8)
    const int t0 = blockIdx.x * 64;
    const int h  = blockIdx.y;
    const int qb = blockIdx.z;       // q*BB + b
    const int b  = qb & (BB - 1);

    const int baseQ = (qb*TT + t0) * 512 + h*64;
    // Load Q tile transposed (k-major), folding in 1/sqrt(DK)=0.125
#pragma unroll
    for (int u = 0; u < 8; u++) {
        int f = tid + 128*u;         // 0..1023
        int m = f >> 4;              // 0..63
        int seg = f & 15;            // float4 within row
        float4 v = *(const float4*)&g_q[baseQ + m*512 + seg*4];
        qs[(seg*4+0)*QS_STRIDE + m] = v.x * 0.125f;
        qs[(seg*4+1)*QS_STRIDE + m] = v.y * 0.125f;
        qs[(seg*4+2)*QS_STRIDE + m] = v.z * 0.125f;
        qs[(seg*4+3)*QS_STRIDE + m] = v.w * 0.125f;
    }

    u64 acc2[4][4], o2[4][4];
    float mrow[8], lrow[8];
#pragma unroll
    for (int i = 0; i < 4; i++)
#pragma unroll
        for (int j = 0; j < 4; j++) { acc2[i][j] = 0ull; o2[i][j] = 0ull; }
#pragma unroll
    for (int i = 0; i < 8; i++) { mrow[i] = -1e30f; lrow[i] = 0.f; }

    for (int c = 0; c < NVAR; c++) {
        const int baseKV = (c*BB + b) * TT * 512 + h*64;
        for (int s0 = 0; s0 < TT; s0 += 64) {
            // Load K (transposed, k-major) and V (direct)
#pragma unroll
            for (int u = 0; u < 8; u++) {
                int f = tid + 128*u;
                int n = f >> 4; int seg = f & 15;
                int gi = baseKV + (s0 + n)*512 + seg*4;
                float4 kv = *(const float4*)&g_k[gi];
                kp[(seg*4+0)*QS_STRIDE + n] = kv.x;
                kp[(seg*4+1)*QS_STRIDE + n] = kv.y;
                kp[(seg*4+2)*QS_STRIDE + n] = kv.z;
                kp[(seg*4+3)*QS_STRIDE + n] = kv.w;
                *(float4*)&vs[n*64 + seg*4] = *(const float4*)&g_v[gi];
            }
            __syncthreads();

            // S = (Q*scale) @ K^T   (64x64, row-pairs packed)
            u64 s2[4][4];
#pragma unroll
            for (int i = 0; i < 4; i++)
#pragma unroll
                for (int j = 0; j < 4; j++) s2[i][j] = 0ull;
#pragma unroll 8
            for (int kk = 0; kk < 64; kk++) {
                ulonglong2 aA = *(const ulonglong2*)&qs[kk*QS_STRIDE + tr*8];
                ulonglong2 aB = *(const ulonglong2*)&qs[kk*QS_STRIDE + tr*8 + 4];
                float4 b4 = *(const float4*)&kp[kk*QS_STRIDE + tc*4];
                u64 ap[4] = {aA.x, aA.y, aB.x, aB.y};
                u64 bd[4] = {dup2(b4.x), dup2(b4.y), dup2(b4.z), dup2(b4.w)};
#pragma unroll
                for (int i = 0; i < 4; i++)
#pragma unroll
                    for (int j = 0; j < 4; j++)
                        s2[i][j] = fma2(ap[i], bd[j], s2[i][j]);
            }
            __syncthreads();  // all K reads done before kp is reused for P

            // unpack S into per-row scalars
            float sfr[8][4];
#pragma unroll
            for (int ip = 0; ip < 4; ip++)
#pragma unroll
                for (int j = 0; j < 4; j++)
                    unpk2(s2[ip][j], sfr[2*ip][j], sfr[2*ip+1][j]);

            // Online softmax (row owned by 16 lanes; xor-shuffle width 16)
            float corrv[8];
#pragma unroll
            for (int i = 0; i < 8; i++) {
                float mx = fmaxf(fmaxf(sfr[i][0], sfr[i][1]),
                                 fmaxf(sfr[i][2], sfr[i][3]));
#pragma unroll
                for (int off = 1; off < 16; off <<= 1)
                    mx = fmaxf(mx, __shfl_xor_sync(0xffffffffu, mx, off));
                float mnew = fmaxf(mrow[i], mx);
                float corr = __expf(mrow[i] - mnew);
                float rs = 0.f;
#pragma unroll
                for (int j = 0; j < 4; j++) {
                    float p = __expf(sfr[i][j] - mnew);
                    sfr[i][j] = p; rs += p;
                }
#pragma unroll
                for (int off = 1; off < 16; off <<= 1)
                    rs += __shfl_xor_sync(0xffffffffu, rs, off);
                lrow[i] = lrow[i]*corr + rs;
                mrow[i] = mnew;
                corrv[i] = corr;
            }
            // rescale O accumulator (packed row-pairs)
#pragma unroll
            for (int ip = 0; ip < 4; ip++) {
                u64 c2 = pack2(corrv[2*ip], corrv[2*ip+1]);
#pragma unroll
                for (int j = 0; j < 4; j++) o2[ip][j] = mul2(o2[ip][j], c2);
            }
            // store P transposed Ps[s][m] — vectorized: thread owns 8
            // consecutive m per s-column -> 2 STS.128 per column, no conflicts
#pragma unroll
            for (int j = 0; j < 4; j++) {
                float* dst = &kp[(tc*4 + j)*QS_STRIDE + tr*8];
                *(float4*)dst =
                    make_float4(sfr[0][j], sfr[1][j], sfr[2][j], sfr[3][j]);
                *(float4*)(dst + 4) =
                    make_float4(sfr[4][j], sfr[5][j], sfr[6][j], sfr[7][j]);
            }
            __syncthreads();

            // O += P @ V  (row-pairs packed)
#pragma unroll 8
            for (int ss = 0; ss < 64; ss++) {
                ulonglong2 pA = *(const ulonglong2*)&kp[ss*QS_STRIDE + tr*8];
                ulonglong2 pB = *(const ulonglong2*)&kp[ss*QS_STRIDE + tr*8 + 4];
                float4 vv = *(const float4*)&vs[ss*64 + tc*4];
                u64 pp[4] = {pA.x, pA.y, pB.x, pB.y};
                u64 vd[4] = {dup2(vv.x), dup2(vv.y), dup2(vv.z), dup2(vv.w)};
#pragma unroll
                for (int i = 0; i < 4; i++)
#pragma unroll
                    for (int j = 0; j < 4; j++)
                        o2[i][j] = fma2(pp[i], vd[j], o2[i][j]);
            }
            __syncthreads();  // before next tile overwrites kp/vs
        }
        // fold this key-variable into the accumulator
#pragma unroll
        for (int ip = 0; ip < 4; ip++) {
            u64 il2 = pack2(1.f / lrow[2*ip], 1.f / lrow[2*ip+1]);
#pragma unroll
            for (int j = 0; j < 4; j++) {
                acc2[ip][j] = fma2(o2[ip][j], il2, acc2[ip][j]);
                o2[ip][j] = 0ull;
            }
        }
#pragma unroll
        for (int i = 0; i < 8; i++) { mrow[i] = -1e30f; lrow[i] = 0.f; }
    }

    // write ctx_sum: [qb, t, h*64+dv]
    const int baseO = (qb*TT + t0) * 512 + h*64;
#pragma unroll
    for (int ip = 0; ip < 4; ip++) {
        float r0[4], r1[4];
#pragma unroll
        for (int j = 0; j < 4; j++) unpk2(acc2[ip][j], r0[j], r1[j]);
        *(float4*)&g_ctx[baseO + (tr*8 + 2*ip+0)*512 + tc*4] =
            make_float4(r0[0], r0[1], r0[2], r0[3]);
        *(float4*)&g_ctx[baseO + (tr*8 + 2*ip+1)*512 + tc*4] =
            make_float4(r1[0], r1[1], r1[2], r1[3]);
    }
}

// ---------------------------------------------------------------------------
// LayerNorm: one block per row of 512
// ---------------------------------------------------------------------------
__global__ __launch_bounds__(128) void ln_kernel(const float* __restrict__ gamma,
                                                 const float* __restrict__ beta,
                                                 float* __restrict__ out)
{
    const int row = blockIdx.x;
    const int t = threadIdx.x;
    float4 v = *(const float4*)&g_res[row*512 + t*4];
    float s  = v.x + v.y + v.z + v.w;
    float ss = v.x*v.x + v.y*v.y + v.z*v.z + v.w*v.w;
#pragma unroll
    for (int off = 16; off; off >>= 1) {
        s  += __shfl_xor_sync(0xffffffffu, s, off);
        ss += __shfl_xor_sync(0xffffffffu, ss, off);
    }
    __shared__ float as[4], ass[4];
    if ((t & 31) == 0) { as[t >> 5] = s; ass[t >> 5] = ss; }
    __syncthreads();
    s  = as[0] + as[1] + as[2] + as[3];
    ss = ass[0] + ass[1] + ass[2] + ass[3];
    float mu  = s * (1.f / 512.f);
    float var = ss * (1.f / 512.f) - mu * mu;
    float inv = rsqrtf(var + 1e-5f);
    float4 g = *(const float4*)&gamma[t*4];
    float4 bb = *(const float4*)&beta[t*4];
    float4 o4;
    o4.x = (v.x - mu)*inv*g.x + bb.x;
    o4.y = (v.y - mu)*inv*g.y + bb.y;
    o4.z = (v.z - mu)*inv*g.z + bb.z;
    o4.w = (v.w - mu)*inv*g.w + bb.w;
    *(float4*)&out[row*512 + t*4] = o4;
}

extern "C" void kernel_launch(void* const* d_in, const int* in_sizes, int n_in,
                              void* d_out, int out_size)
{
    const float* x     = (const float*)d_in[0];
    const float* Wq    = (const float*)d_in[1];
    const float* bq    = (const float*)d_in[2];
    const float* Wk    = (const float*)d_in[3];
    const float* bk    = (const float*)d_in[4];
    const float* Wv    = (const float*)d_in[5];
    const float* bv    = (const float*)d_in[6];
    const float* Wo    = (const float*)d_in[7];
    const float* bo    = (const float*)d_in[8];
    const float* gamma = (const float*)d_in[9];
    const float* beta  = (const float*)d_in[10];
    float* out = (float*)d_out;

    const int attn_smem = (64*QS_STRIDE*2 + 64*64) * (int)sizeof(float);  // 51200
    cudaFuncSetAttribute(attn_kernel, cudaFuncAttributeMaxDynamicSharedMemorySize,
                         attn_smem);

    qkv_gemm<<<dim3(512/64, MROWS/128, 3), 256>>>(x, Wq, bq, Wk, bk, Wv, bv);
    attn_kernel<<<dim3(TT/64, HH, NVAR*BB), 128, attn_smem>>>();
    out_gemm<<<dim3(512/64, MROWS/128, 1), 256>>>(Wo, bo, x);
    ln_kernel<<<MROWS, 128>>>(gamma, beta, out);
}

// round 7
// speedup vs baseline: 1.3217x; 1.1252x over previous
#include <cuda_runtime.h>
#include <cuda_bf16.h>
#include <cstdint>
#include <math.h>

#define NVAR 4
#define BB   4
#define TT   512
#define DD   512
#define HH   8
#define MROWS (NVAR*BB*TT)   // 8192

// Scratch (alloc-free rule: __device__ globals)
__device__ float g_q[MROWS*DD];
__device__ float g_k[MROWS*DD];
__device__ float g_v[MROWS*DD];
__device__ float g_res[MROWS*DD];
// bf16 split operands for HMMA GEMMs
__device__ __nv_bfloat16 g_xh[MROWS*DD],   g_xl[MROWS*DD];
__device__ __nv_bfloat16 g_ctxh[MROWS*DD], g_ctxl[MROWS*DD];
__device__ __nv_bfloat16 g_wh[4*DD*DD],    g_wl[4*DD*DD];   // [w][n][k] (transposed)

// ------------------------- packed f32x2 helpers ----------------------------
typedef unsigned long long u64;

__device__ __forceinline__ u64 pack2(float lo, float hi) {
    u64 r; asm("mov.b64 %0, {%1, %2};" : "=l"(r) : "f"(lo), "f"(hi)); return r;
}
__device__ __forceinline__ u64 dup2(float v) {
    u64 r; asm("mov.b64 %0, {%1, %1};" : "=l"(r) : "f"(v)); return r;
}
__device__ __forceinline__ void unpk2(u64 p, float& lo, float& hi) {
    asm("mov.b64 {%0, %1}, %2;" : "=f"(lo), "=f"(hi) : "l"(p));
}
__device__ __forceinline__ u64 fma2(u64 a, u64 b, u64 c) {
    u64 d; asm("fma.rn.f32x2 %0, %1, %2, %3;" : "=l"(d) : "l"(a), "l"(b), "l"(c)); return d;
}
__device__ __forceinline__ u64 mul2(u64 a, u64 b) {
    u64 d; asm("mul.rn.f32x2 %0, %1, %2;" : "=l"(d) : "l"(a), "l"(b)); return d;
}

// ------------------------- warp mma (portable PTX, sm_80+) -----------------
__device__ __forceinline__ void mma_bf16(float* c, const uint32_t* a,
                                         const uint32_t* b) {
    asm volatile(
        "mma.sync.aligned.m16n8k16.row.col.f32.bf16.bf16.f32 "
        "{%0,%1,%2,%3}, {%4,%5,%6,%7}, {%8,%9}, {%0,%1,%2,%3};"
        : "+f"(c[0]), "+f"(c[1]), "+f"(c[2]), "+f"(c[3])
        : "r"(a[0]), "r"(a[1]), "r"(a[2]), "r"(a[3]), "r"(b[0]), "r"(b[1]));
}

// ---------------------------------------------------------------------------
// prep kernels: bf16 hi/lo split of x; transpose+split of weights
// ---------------------------------------------------------------------------
__device__ __forceinline__ void split_store(__nv_bfloat16* H, __nv_bfloat16* L,
                                            int idx, const float* r) {
#pragma unroll
    for (int j = 0; j < 4; j += 2) {
        __nv_bfloat16 h0 = __float2bfloat16_rn(r[j]);
        __nv_bfloat16 h1 = __float2bfloat16_rn(r[j+1]);
        __nv_bfloat16 l0 = __float2bfloat16_rn(r[j]   - __bfloat162float(h0));
        __nv_bfloat16 l1 = __float2bfloat16_rn(r[j+1] - __bfloat162float(h1));
        __nv_bfloat162 hp; hp.x = h0; hp.y = h1;
        __nv_bfloat162 lp; lp.x = l0; lp.y = l1;
        *(__nv_bfloat162*)&H[idx + j] = hp;
        *(__nv_bfloat162*)&L[idx + j] = lp;
    }
}

__global__ __launch_bounds__(256) void prep_x_kernel(const float* __restrict__ x) {
    int i4 = blockIdx.x * blockDim.x + threadIdx.x;   // float4 index
    float4 v = *(const float4*)&x[i4 * 4];
    float r[4] = {v.x, v.y, v.z, v.w};
    split_store(g_xh, g_xl, i4 * 4, r);
}

__global__ __launch_bounds__(256) void prep_w_kernel(
    const float* __restrict__ Wq, const float* __restrict__ Wk,
    const float* __restrict__ Wv, const float* __restrict__ Wo)
{
    __shared__ float tile[32][33];
    const int w = blockIdx.z;
    const float* W = (w == 0) ? Wq : (w == 1) ? Wk : (w == 2) ? Wv : Wo;
    const int k0 = blockIdx.x * 32, n0 = blockIdx.y * 32;
    const int tx = threadIdx.x, ty = threadIdx.y;   // block (32, 8)
#pragma unroll
    for (int i = 0; i < 32; i += 8)
        tile[ty + i][tx] = W[(k0 + ty + i) * 512 + n0 + tx];
    __syncthreads();
    __nv_bfloat16* H = g_wh + w * DD * DD;
    __nv_bfloat16* L = g_wl + w * DD * DD;
#pragma unroll
    for (int i = 0; i < 32; i += 8) {
        float v = tile[tx][ty + i];
        __nv_bfloat16 h = __float2bfloat16_rn(v);
        __nv_bfloat16 l = __float2bfloat16_rn(v - __bfloat162float(h));
        int idx = (n0 + ty + i) * 512 + k0 + tx;
        H[idx] = h; L[idx] = l;
    }
}

// ---------------------------------------------------------------------------
// HMMA bf16-split GEMM: C[128x64] = scale*(A@W^T) + bias (+ resid)
// A hi/lo: [M,512] bf16 row-major. W hi/lo: [N,K] bf16 (pre-transposed).
// 256 threads = 8 warps in 4(M)x2(N); warp tile 32x32 via m16n8k16.
// smem rows padded to 40 bf16 -> conflict-free LDS.32 fragment fetch.
// ---------------------------------------------------------------------------
#define LDK 40
__device__ __forceinline__ void hmma_gemm_body(
    const __nv_bfloat16* __restrict__ Ah, const __nv_bfloat16* __restrict__ Al,
    const __nv_bfloat16* __restrict__ Wh, const __nv_bfloat16* __restrict__ Wl,
    const float* __restrict__ bias, const float* __restrict__ resid,
    float scale, float* __restrict__ C)
{
    __shared__ __nv_bfloat16 sAh[128*LDK], sAl[128*LDK];
    __shared__ __nv_bfloat16 sBh[64*LDK],  sBl[64*LDK];

    const int tid = threadIdx.x;
    const int lane = tid & 31;
    const int warp = tid >> 5;
    const int warpM = warp >> 1;          // 0..3
    const int warpN = warp & 1;           // 0..1
    const int g   = lane >> 2;            // group id 0..7
    const int tig = lane & 3;             // thread in group
    const int bm0 = blockIdx.y * 128;
    const int bn0 = blockIdx.x * 64;

    float acc[2][4][4];
#pragma unroll
    for (int mt = 0; mt < 2; mt++)
#pragma unroll
        for (int nt = 0; nt < 4; nt++)
#pragma unroll
            for (int r = 0; r < 4; r++) acc[mt][nt][r] = 0.f;

    for (int k0 = 0; k0 < 512; k0 += 32) {
        // A: 128x32 bf16 (hi+lo) = 512 uint4 each; 2 per thread
#pragma unroll
        for (int r = 0; r < 2; r++) {
            int f = r * 256 + tid;
            int row = f >> 2, seg = f & 3;
            *(uint4*)&sAh[row*LDK + seg*8] =
                *(const uint4*)&Ah[(bm0 + row)*512 + k0 + seg*8];
            *(uint4*)&sAl[row*LDK + seg*8] =
                *(const uint4*)&Al[(bm0 + row)*512 + k0 + seg*8];
        }
        // B: 64x32 bf16 (hi+lo) = 256 uint4 each; 1 per thread
        {
            int row = tid >> 2, seg = tid & 3;
            *(uint4*)&sBh[row*LDK + seg*8] =
                *(const uint4*)&Wh[(bn0 + row)*512 + k0 + seg*8];
            *(uint4*)&sBl[row*LDK + seg*8] =
                *(const uint4*)&Wl[(bn0 + row)*512 + k0 + seg*8];
        }
        __syncthreads();

#pragma unroll
        for (int kk = 0; kk < 32; kk += 16) {
            uint32_t ah[2][4], al[2][4];
#pragma unroll
            for (int mt = 0; mt < 2; mt++) {
                int rb = warpM*32 + mt*16;
                int ka = kk + 2*tig;
                ah[mt][0] = *(const uint32_t*)&sAh[(rb + g    )*LDK + ka];
                ah[mt][1] = *(const uint32_t*)&sAh[(rb + g + 8)*LDK + ka];
                ah[mt][2] = *(const uint32_t*)&sAh[(rb + g    )*LDK + ka + 8];
                ah[mt][3] = *(const uint32_t*)&sAh[(rb + g + 8)*LDK + ka + 8];
                al[mt][0] = *(const uint32_t*)&sAl[(rb + g    )*LDK + ka];
                al[mt][1] = *(const uint32_t*)&sAl[(rb + g + 8)*LDK + ka];
                al[mt][2] = *(const uint32_t*)&sAl[(rb + g    )*LDK + ka + 8];
                al[mt][3] = *(const uint32_t*)&sAl[(rb + g + 8)*LDK + ka + 8];
            }
            uint32_t bh[4][2], bl[4][2];
#pragma unroll
            for (int nt = 0; nt < 4; nt++) {
                int n = warpN*32 + nt*8 + g;
                int kb = kk + 2*tig;
                bh[nt][0] = *(const uint32_t*)&sBh[n*LDK + kb];
                bh[nt][1] = *(const uint32_t*)&sBh[n*LDK + kb + 8];
                bl[nt][0] = *(const uint32_t*)&sBl[n*LDK + kb];
                bl[nt][1] = *(const uint32_t*)&sBl[n*LDK + kb + 8];
            }
#pragma unroll
            for (int mt = 0; mt < 2; mt++)
#pragma unroll
                for (int nt = 0; nt < 4; nt++) {
                    mma_bf16(acc[mt][nt], ah[mt], bh[nt]);
                    mma_bf16(acc[mt][nt], ah[mt], bl[nt]);
                    mma_bf16(acc[mt][nt], al[mt], bh[nt]);
                }
        }
        __syncthreads();
    }

    // epilogue: fragment rows g / g+8, cols 2*tig..2*tig+1
#pragma unroll
    for (int mt = 0; mt < 2; mt++)
#pragma unroll
        for (int nt = 0; nt < 4; nt++) {
            const float* ac = acc[mt][nt];
            int r0 = bm0 + warpM*32 + mt*16 + g;
            int cc = bn0 + warpN*32 + nt*8 + 2*tig;
            float2 bb = *(const float2*)&bias[cc];
            float2 o0, o1;
            o0.x = ac[0]*scale + bb.x;  o0.y = ac[1]*scale + bb.y;
            o1.x = ac[2]*scale + bb.x;  o1.y = ac[3]*scale + bb.y;
            if (resid) {
                float2 q0 = *(const float2*)&resid[r0*512 + cc];
                float2 q1 = *(const float2*)&resid[(r0+8)*512 + cc];
                o0.x += q0.x; o0.y += q0.y;
                o1.x += q1.x; o1.y += q1.y;
            }
            *(float2*)&C[r0*512 + cc]     = o0;
            *(float2*)&C[(r0+8)*512 + cc] = o1;
        }
}

__global__ __launch_bounds__(256) void hmma_qkv(
    const float* __restrict__ bq, const float* __restrict__ bk,
    const float* __restrict__ bv)
{
    int w = blockIdx.z;
    const float* bias = (w == 0) ? bq : (w == 1) ? bk : bv;
    float* C = (w == 0) ? g_q : (w == 1) ? g_k : g_v;
    hmma_gemm_body(g_xh, g_xl, g_wh + w * DD * DD, g_wl + w * DD * DD,
                   bias, nullptr, 1.0f, C);
}

__global__ __launch_bounds__(256) void hmma_out(
    const float* __restrict__ bo, const float* __restrict__ x)
{
    hmma_gemm_body(g_ctxh, g_ctxl, g_wh + 3 * DD * DD, g_wl + 3 * DD * DD,
                   bo, x, 1.0f / (float)NVAR, g_res);
}

// ---------------------------------------------------------------------------
// Flash attention over 4 key-variables (scalar FFMA2 path; epilogue stores
// ctx as bf16 hi/lo split feeding the HMMA out-projection).
// ---------------------------------------------------------------------------
#define QS_STRIDE 68
__global__ __launch_bounds__(128) void attn_kernel()
{
    extern __shared__ float sm[];
    float* qs = sm;                 // 64*68
    float* kp = sm + 64*QS_STRIDE;  // 64*68 (K tile then P tile)
    float* vs = kp + 64*QS_STRIDE;  // 64*64

    const int tid = threadIdx.x;
    const int tc = tid & 15;
    const int tr = tid >> 4;
    const int t0 = blockIdx.x * 64;
    const int h  = blockIdx.y;
    const int qb = blockIdx.z;
    const int b  = qb & (BB - 1);

    const int baseQ = (qb*TT + t0) * 512 + h*64;
#pragma unroll
    for (int u = 0; u < 8; u++) {
        int f = tid + 128*u;
        int m = f >> 4;
        int seg = f & 15;
        float4 v = *(const float4*)&g_q[baseQ + m*512 + seg*4];
        qs[(seg*4+0)*QS_STRIDE + m] = v.x * 0.125f;
        qs[(seg*4+1)*QS_STRIDE + m] = v.y * 0.125f;
        qs[(seg*4+2)*QS_STRIDE + m] = v.z * 0.125f;
        qs[(seg*4+3)*QS_STRIDE + m] = v.w * 0.125f;
    }

    u64 acc2[4][4], o2[4][4];
    float mrow[8], lrow[8];
#pragma unroll
    for (int i = 0; i < 4; i++)
#pragma unroll
        for (int j = 0; j < 4; j++) { acc2[i][j] = 0ull; o2[i][j] = 0ull; }
#pragma unroll
    for (int i = 0; i < 8; i++) { mrow[i] = -1e30f; lrow[i] = 0.f; }

    for (int c = 0; c < NVAR; c++) {
        const int baseKV = (c*BB + b) * TT * 512 + h*64;
        for (int s0 = 0; s0 < TT; s0 += 64) {
#pragma unroll
            for (int u = 0; u < 8; u++) {
                int f = tid + 128*u;
                int n = f >> 4; int seg = f & 15;
                int gi = baseKV + (s0 + n)*512 + seg*4;
                float4 kv = *(const float4*)&g_k[gi];
                kp[(seg*4+0)*QS_STRIDE + n] = kv.x;
                kp[(seg*4+1)*QS_STRIDE + n] = kv.y;
                kp[(seg*4+2)*QS_STRIDE + n] = kv.z;
                kp[(seg*4+3)*QS_STRIDE + n] = kv.w;
                *(float4*)&vs[n*64 + seg*4] = *(const float4*)&g_v[gi];
            }
            __syncthreads();

            u64 s2[4][4];
#pragma unroll
            for (int i = 0; i < 4; i++)
#pragma unroll
                for (int j = 0; j < 4; j++) s2[i][j] = 0ull;
#pragma unroll 8
            for (int kk = 0; kk < 64; kk++) {
                ulonglong2 aA = *(const ulonglong2*)&qs[kk*QS_STRIDE + tr*8];
                ulonglong2 aB = *(const ulonglong2*)&qs[kk*QS_STRIDE + tr*8 + 4];
                float4 b4 = *(const float4*)&kp[kk*QS_STRIDE + tc*4];
                u64 ap[4] = {aA.x, aA.y, aB.x, aB.y};
                u64 bd[4] = {dup2(b4.x), dup2(b4.y), dup2(b4.z), dup2(b4.w)};
#pragma unroll
                for (int i = 0; i < 4; i++)
#pragma unroll
                    for (int j = 0; j < 4; j++)
                        s2[i][j] = fma2(ap[i], bd[j], s2[i][j]);
            }
            __syncthreads();

            float sfr[8][4];
#pragma unroll
            for (int ip = 0; ip < 4; ip++)
#pragma unroll
                for (int j = 0; j < 4; j++)
                    unpk2(s2[ip][j], sfr[2*ip][j], sfr[2*ip+1][j]);

            float corrv[8];
#pragma unroll
            for (int i = 0; i < 8; i++) {
                float mx = fmaxf(fmaxf(sfr[i][0], sfr[i][1]),
                                 fmaxf(sfr[i][2], sfr[i][3]));
#pragma unroll
                for (int off = 1; off < 16; off <<= 1)
                    mx = fmaxf(mx, __shfl_xor_sync(0xffffffffu, mx, off));
                float mnew = fmaxf(mrow[i], mx);
                float corr = __expf(mrow[i] - mnew);
                float rs = 0.f;
#pragma unroll
                for (int j = 0; j < 4; j++) {
                    float p = __expf(sfr[i][j] - mnew);
                    sfr[i][j] = p; rs += p;
                }
#pragma unroll
                for (int off = 1; off < 16; off <<= 1)
                    rs += __shfl_xor_sync(0xffffffffu, rs, off);
                lrow[i] = lrow[i]*corr + rs;
                mrow[i] = mnew;
                corrv[i] = corr;
            }
#pragma unroll
            for (int ip = 0; ip < 4; ip++) {
                u64 c2 = pack2(corrv[2*ip], corrv[2*ip+1]);
#pragma unroll
                for (int j = 0; j < 4; j++) o2[ip][j] = mul2(o2[ip][j], c2);
            }
#pragma unroll
            for (int j = 0; j < 4; j++) {
                float* dst = &kp[(tc*4 + j)*QS_STRIDE + tr*8];
                *(float4*)dst =
                    make_float4(sfr[0][j], sfr[1][j], sfr[2][j], sfr[3][j]);
                *(float4*)(dst + 4) =
                    make_float4(sfr[4][j], sfr[5][j], sfr[6][j], sfr[7][j]);
            }
            __syncthreads();

#pragma unroll 8
            for (int ss = 0; ss < 64; ss++) {
                ulonglong2 pA = *(const ulonglong2*)&kp[ss*QS_STRIDE + tr*8];
                ulonglong2 pB = *(const ulonglong2*)&kp[ss*QS_STRIDE + tr*8 + 4];
                float4 vv = *(const float4*)&vs[ss*64 + tc*4];
                u64 pp[4] = {pA.x, pA.y, pB.x, pB.y};
                u64 vd[4] = {dup2(vv.x), dup2(vv.y), dup2(vv.z), dup2(vv.w)};
#pragma unroll
                for (int i = 0; i < 4; i++)
#pragma unroll
                    for (int j = 0; j < 4; j++)
                        o2[i][j] = fma2(pp[i], vd[j], o2[i][j]);
            }
            __syncthreads();
        }
#pragma unroll
        for (int ip = 0; ip < 4; ip++) {
            u64 il2 = pack2(1.f / lrow[2*ip], 1.f / lrow[2*ip+1]);
#pragma unroll
            for (int j = 0; j < 4; j++) {
                acc2[ip][j] = fma2(o2[ip][j], il2, acc2[ip][j]);
                o2[ip][j] = 0ull;
            }
        }
#pragma unroll
        for (int i = 0; i < 8; i++) { mrow[i] = -1e30f; lrow[i] = 0.f; }
    }

    // write ctx_sum as bf16 hi/lo split (feeds HMMA out-projection)
    const int baseO = (qb*TT + t0) * 512 + h*64;
#pragma unroll
    for (int ip = 0; ip < 4; ip++) {
        float r0[4], r1[4];
#pragma unroll
        for (int j = 0; j < 4; j++) unpk2(acc2[ip][j], r0[j], r1[j]);
        split_store(g_ctxh, g_ctxl, baseO + (tr*8 + 2*ip+0)*512 + tc*4, r0);
        split_store(g_ctxh, g_ctxl, baseO + (tr*8 + 2*ip+1)*512 + tc*4, r1);
    }
}

// ---------------------------------------------------------------------------
// LayerNorm: one block per row of 512
// ---------------------------------------------------------------------------
__global__ __launch_bounds__(128) void ln_kernel(const float* __restrict__ gamma,
                                                 const float* __restrict__ beta,
                                                 float* __restrict__ out)
{
    const int row = blockIdx.x;
    const int t = threadIdx.x;
    float4 v = *(const float4*)&g_res[row*512 + t*4];
    float s  = v.x + v.y + v.z + v.w;
    float ss = v.x*v.x + v.y*v.y + v.z*v.z + v.w*v.w;
#pragma unroll
    for (int off = 16; off; off >>= 1) {
        s  += __shfl_xor_sync(0xffffffffu, s, off);
        ss += __shfl_xor_sync(0xffffffffu, ss, off);
    }
    __shared__ float as[4], ass[4];
    if ((t & 31) == 0) { as[t >> 5] = s; ass[t >> 5] = ss; }
    __syncthreads();
    s  = as[0] + as[1] + as[2] + as[3];
    ss = ass[0] + ass[1] + ass[2] + ass[3];
    float mu  = s * (1.f / 512.f);
    float var = ss * (1.f / 512.f) - mu * mu;
    float inv = rsqrtf(var + 1e-5f);
    float4 g = *(const float4*)&gamma[t*4];
    float4 bb = *(const float4*)&beta[t*4];
    float4 o4;
    o4.x = (v.x - mu)*inv*g.x + bb.x;
    o4.y = (v.y - mu)*inv*g.y + bb.y;
    o4.z = (v.z - mu)*inv*g.z + bb.z;
    o4.w = (v.w - mu)*inv*g.w + bb.w;
    *(float4*)&out[row*512 + t*4] = o4;
}

extern "C" void kernel_launch(void* const* d_in, const int* in_sizes, int n_in,
                              void* d_out, int out_size)
{
    const float* x     = (const float*)d_in[0];
    const float* Wq    = (const float*)d_in[1];
    const float* bq    = (const float*)d_in[2];
    const float* Wk    = (const float*)d_in[3];
    const float* bk    = (const float*)d_in[4];
    const float* Wv    = (const float*)d_in[5];
    const float* bv    = (const float*)d_in[6];
    const float* Wo    = (const float*)d_in[7];
    const float* bo    = (const float*)d_in[8];
    const float* gamma = (const float*)d_in[9];
    const float* beta  = (const float*)d_in[10];
    float* out = (float*)d_out;

    const int attn_smem = (64*QS_STRIDE*2 + 64*64) * (int)sizeof(float);  // 51200
    cudaFuncSetAttribute(attn_kernel, cudaFuncAttributeMaxDynamicSharedMemorySize,
                         attn_smem);

    prep_x_kernel<<<MROWS*DD/4/256, 256>>>(x);
    prep_w_kernel<<<dim3(16, 16, 4), dim3(32, 8)>>>(Wq, Wk, Wv, Wo);
    hmma_qkv<<<dim3(512/64, MROWS/128, 3), 256>>>(bq, bk, bv);
    attn_kernel<<<dim3(TT/64, HH, NVAR*BB), 128, attn_smem>>>();
    hmma_out<<<dim3(512/64, MROWS/128, 1), 256>>>(bo, x);
    ln_kernel<<<MROWS, 128>>>(gamma, beta, out);
}

// round 9
// speedup vs baseline: 2.2659x; 1.7144x over previous
#include <cuda_runtime.h>
#include <cuda_bf16.h>
#include <cstdint>
#include <math.h>

#define NVAR 4
#define BB   4
#define TT   512
#define DD   512
#define HH   8
#define MROWS (NVAR*BB*TT)   // 8192

// Scratch (alloc-free rule: __device__ globals)
__device__ float g_res[MROWS*DD];
// bf16 hi/lo split operands
__device__ __nv_bfloat16 g_xh[MROWS*DD],   g_xl[MROWS*DD];
__device__ __nv_bfloat16 g_qh[MROWS*DD],   g_ql[MROWS*DD];    // Q*0.125, [tok][h*64+dk]
__device__ __nv_bfloat16 g_kh[MROWS*DD],   g_kl[MROWS*DD];    // K, [tok][h*64+dk]
__device__ __nv_bfloat16 g_vTh[MROWS*DD],  g_vTl[MROWS*DD];   // V^T, [(cb*8+h)*64+dv][t]
__device__ __nv_bfloat16 g_ctxh[MROWS*DD], g_ctxl[MROWS*DD];  // ctx_sum, [tok][h*64+dv]
__device__ __nv_bfloat16 g_wh[4*DD*DD],    g_wl[4*DD*DD];     // weights [w][n][k]

// ------------------------- helpers ----------------------------------------
__device__ __forceinline__ void mma_bf16(float* c, const uint32_t* a,
                                         const uint32_t* b) {
    asm volatile(
        "mma.sync.aligned.m16n8k16.row.col.f32.bf16.bf16.f32 "
        "{%0,%1,%2,%3}, {%4,%5,%6,%7}, {%8,%9}, {%0,%1,%2,%3};"
        : "+f"(c[0]), "+f"(c[1]), "+f"(c[2]), "+f"(c[3])
        : "r"(a[0]), "r"(a[1]), "r"(a[2]), "r"(a[3]), "r"(b[0]), "r"(b[1]));
}
__device__ __forceinline__ uint32_t cvt_bf2(float hi_v, float lo_v) {
    uint32_t r;
    asm("cvt.rn.bf16x2.f32 %0, %1, %2;" : "=r"(r) : "f"(hi_v), "f"(lo_v));
    return r;
}
// split pair (x0->lo half, x1->hi half) into bf16x2 hi + bf16x2 lo-residual
__device__ __forceinline__ void bsplit2(float x0, float x1,
                                        uint32_t& h, uint32_t& l) {
    h = cvt_bf2(x1, x0);
    float h0 = __uint_as_float(h << 16);
    float h1 = __uint_as_float(h & 0xffff0000u);
    l = cvt_bf2(x1 - h1, x0 - h0);
}
__device__ __forceinline__ void split_store(__nv_bfloat16* H, __nv_bfloat16* L,
                                            int idx, const float* r) {
#pragma unroll
    for (int j = 0; j < 4; j += 2) {
        uint32_t h, l;
        bsplit2(r[j], r[j+1], h, l);
        *(uint32_t*)&H[idx + j] = h;
        *(uint32_t*)&L[idx + j] = l;
    }
}

// ---------------------------------------------------------------------------
// prep kernels
// ---------------------------------------------------------------------------
__global__ __launch_bounds__(256) void prep_x_kernel(const float* __restrict__ x) {
    int i4 = blockIdx.x * blockDim.x + threadIdx.x;
    float4 v = *(const float4*)&x[i4 * 4];
    float r[4] = {v.x, v.y, v.z, v.w};
    split_store(g_xh, g_xl, i4 * 4, r);
}

__global__ __launch_bounds__(256) void prep_w_kernel(
    const float* __restrict__ Wq, const float* __restrict__ Wk,
    const float* __restrict__ Wv, const float* __restrict__ Wo)
{
    __shared__ float tile[32][33];
    const int w = blockIdx.z;
    const float* W = (w == 0) ? Wq : (w == 1) ? Wk : (w == 2) ? Wv : Wo;
    const int k0 = blockIdx.x * 32, n0 = blockIdx.y * 32;
    const int tx = threadIdx.x, ty = threadIdx.y;   // (32, 8)
#pragma unroll
    for (int i = 0; i < 32; i += 8)
        tile[ty + i][tx] = W[(k0 + ty + i) * 512 + n0 + tx];
    __syncthreads();
    __nv_bfloat16* H = g_wh + w * DD * DD;
    __nv_bfloat16* L = g_wl + w * DD * DD;
#pragma unroll
    for (int i = 0; i < 32; i += 8) {
        float v = tile[tx][ty + i];
        __nv_bfloat16 h = __float2bfloat16_rn(v);
        __nv_bfloat16 l = __float2bfloat16_rn(v - __bfloat162float(h));
        int idx = (n0 + ty + i) * 512 + k0 + tx;
        H[idx] = h; L[idx] = l;
    }
}

// ---------------------------------------------------------------------------
// HMMA bf16-split GEMM, 128x64 tile, 8 warps (4M x 2N), warp tile 32x32.
// mode 0: C = acc*scale + bias + resid (fp32, out-proj)
// mode 1: split-store (acc + bias)*scale -> H/L at [row*512+col]
// mode 2: split-store (acc + bias) -> V^T layout in H/L
// ---------------------------------------------------------------------------
#define LDK 40
__device__ __forceinline__ void hmma_gemm_body(
    const __nv_bfloat16* __restrict__ Ah, const __nv_bfloat16* __restrict__ Al,
    const __nv_bfloat16* __restrict__ Wh, const __nv_bfloat16* __restrict__ Wl,
    const float* __restrict__ bias, const float* __restrict__ resid,
    float scale, int mode, float* __restrict__ C,
    __nv_bfloat16* __restrict__ Hd, __nv_bfloat16* __restrict__ Ld)
{
    __shared__ __nv_bfloat16 sAh[128*LDK], sAl[128*LDK];
    __shared__ __nv_bfloat16 sBh[64*LDK],  sBl[64*LDK];

    const int tid = threadIdx.x;
    const int lane = tid & 31;
    const int warp = tid >> 5;
    const int warpM = warp >> 1;
    const int warpN = warp & 1;
    const int g   = lane >> 2;
    const int tig = lane & 3;
    const int bm0 = blockIdx.y * 128;
    const int bn0 = blockIdx.x * 64;

    float acc[2][4][4];
#pragma unroll
    for (int mt = 0; mt < 2; mt++)
#pragma unroll
        for (int nt = 0; nt < 4; nt++)
#pragma unroll
            for (int r = 0; r < 4; r++) acc[mt][nt][r] = 0.f;

    for (int k0 = 0; k0 < 512; k0 += 32) {
#pragma unroll
        for (int r = 0; r < 2; r++) {
            int f = r * 256 + tid;
            int row = f >> 2, seg = f & 3;
            *(uint4*)&sAh[row*LDK + seg*8] =
                *(const uint4*)&Ah[(bm0 + row)*512 + k0 + seg*8];
            *(uint4*)&sAl[row*LDK + seg*8] =
                *(const uint4*)&Al[(bm0 + row)*512 + k0 + seg*8];
        }
        {
            int row = tid >> 2, seg = tid & 3;
            *(uint4*)&sBh[row*LDK + seg*8] =
                *(const uint4*)&Wh[(bn0 + row)*512 + k0 + seg*8];
            *(uint4*)&sBl[row*LDK + seg*8] =
                *(const uint4*)&Wl[(bn0 + row)*512 + k0 + seg*8];
        }
        __syncthreads();

#pragma unroll
        for (int kk = 0; kk < 32; kk += 16) {
            uint32_t ah[2][4], al[2][4];
#pragma unroll
            for (int mt = 0; mt < 2; mt++) {
                int rb = warpM*32 + mt*16;
                int ka = kk + 2*tig;
                ah[mt][0] = *(const uint32_t*)&sAh[(rb + g    )*LDK + ka];
                ah[mt][1] = *(const uint32_t*)&sAh[(rb + g + 8)*LDK + ka];
                ah[mt][2] = *(const uint32_t*)&sAh[(rb + g    )*LDK + ka + 8];
                ah[mt][3] = *(const uint32_t*)&sAh[(rb + g + 8)*LDK + ka + 8];
                al[mt][0] = *(const uint32_t*)&sAl[(rb + g    )*LDK + ka];
                al[mt][1] = *(const uint32_t*)&sAl[(rb + g + 8)*LDK + ka];
                al[mt][2] = *(const uint32_t*)&sAl[(rb + g    )*LDK + ka + 8];
                al[mt][3] = *(const uint32_t*)&sAl[(rb + g + 8)*LDK + ka + 8];
            }
            uint32_t bh[4][2], bl[4][2];
#pragma unroll
            for (int nt = 0; nt < 4; nt++) {
                int n = warpN*32 + nt*8 + g;
                int kb = kk + 2*tig;
                bh[nt][0] = *(const uint32_t*)&sBh[n*LDK + kb];
                bh[nt][1] = *(const uint32_t*)&sBh[n*LDK + kb + 8];
                bl[nt][0] = *(const uint32_t*)&sBl[n*LDK + kb];
                bl[nt][1] = *(const uint32_t*)&sBl[n*LDK + kb + 8];
            }
#pragma unroll
            for (int mt = 0; mt < 2; mt++)
#pragma unroll
                for (int nt = 0; nt < 4; nt++) {
                    mma_bf16(acc[mt][nt], ah[mt], bh[nt]);
                    mma_bf16(acc[mt][nt], ah[mt], bl[nt]);
                    mma_bf16(acc[mt][nt], al[mt], bh[nt]);
                }
        }
        __syncthreads();
    }

#pragma unroll
    for (int mt = 0; mt < 2; mt++)
#pragma unroll
        for (int nt = 0; nt < 4; nt++) {
            const float* ac = acc[mt][nt];
            int r0 = bm0 + warpM*32 + mt*16 + g;
            int cc = bn0 + warpN*32 + nt*8 + 2*tig;
            float2 bb = *(const float2*)&bias[cc];
            if (mode == 0) {
                float2 o0, o1;
                o0.x = ac[0]*scale + bb.x;  o0.y = ac[1]*scale + bb.y;
                o1.x = ac[2]*scale + bb.x;  o1.y = ac[3]*scale + bb.y;
                float2 q0 = *(const float2*)&resid[r0*512 + cc];
                float2 q1 = *(const float2*)&resid[(r0+8)*512 + cc];
                o0.x += q0.x; o0.y += q0.y;
                o1.x += q1.x; o1.y += q1.y;
                *(float2*)&C[r0*512 + cc]     = o0;
                *(float2*)&C[(r0+8)*512 + cc] = o1;
            } else if (mode == 1) {
                uint32_t h, l;
                bsplit2((ac[0] + bb.x)*scale, (ac[1] + bb.y)*scale, h, l);
                *(uint32_t*)&Hd[r0*512 + cc] = h;
                *(uint32_t*)&Ld[r0*512 + cc] = l;
                bsplit2((ac[2] + bb.x)*scale, (ac[3] + bb.y)*scale, h, l);
                *(uint32_t*)&Hd[(r0+8)*512 + cc] = h;
                *(uint32_t*)&Ld[(r0+8)*512 + cc] = l;
            } else {
                // V^T scatter: element (token r, col ccx) -> [(cb*8+h)*64+dv][t]
#pragma unroll
                for (int e = 0; e < 4; e++) {
                    int r  = (e < 2) ? r0 : r0 + 8;
                    int cx = cc + (e & 1);
                    float o = ac[e] + ((e & 1) ? bb.y : bb.x);
                    int cb = r >> 9, t = r & 511;
                    int hh = cx >> 6, dv = cx & 63;
                    int addr = (((cb*8 + hh)*64) + dv)*512 + t;
                    __nv_bfloat16 bh16 = __float2bfloat16_rn(o);
                    __nv_bfloat16 bl16 =
                        __float2bfloat16_rn(o - __bfloat162float(bh16));
                    Hd[addr] = bh16; Ld[addr] = bl16;
                }
            }
        }
}

__global__ __launch_bounds__(256) void hmma_qkv(
    const float* __restrict__ bq, const float* __restrict__ bk,
    const float* __restrict__ bv)
{
    int w = blockIdx.z;
    if (w == 0)
        hmma_gemm_body(g_xh, g_xl, g_wh, g_wl, bq, nullptr,
                       0.125f, 1, nullptr, g_qh, g_ql);
    else if (w == 1)
        hmma_gemm_body(g_xh, g_xl, g_wh + DD*DD, g_wl + DD*DD, bk, nullptr,
                       1.0f, 1, nullptr, g_kh, g_kl);
    else
        hmma_gemm_body(g_xh, g_xl, g_wh + 2*DD*DD, g_wl + 2*DD*DD, bv, nullptr,
                       1.0f, 2, nullptr, g_vTh, g_vTl);
}

__global__ __launch_bounds__(256) void hmma_out(
    const float* __restrict__ bo, const float* __restrict__ x)
{
    hmma_gemm_body(g_ctxh, g_ctxl, g_wh + 3*DD*DD, g_wl + 3*DD*DD,
                   bo, x, 1.0f / (float)NVAR, 0, g_res, nullptr, nullptr);
}

// ---------------------------------------------------------------------------
// FA2-style mma.sync attention. Block = 256 thr (8 warps), 128 Q rows per
// block, one (qb, h). Q persistent in registers as A-fragments (hi/lo).
// S = Q@K^T via mma; softmax on fragments; P re-packed to bf16 in registers
// (S-frag layout == A-frag layout); O += P@V with V^T staged from g_vT.
// ---------------------------------------------------------------------------
#define ALD 72
__global__ __launch_bounds__(256) void attn_mma_kernel()
{
    __shared__ __nv_bfloat16 kh[64*ALD], kl[64*ALD], vh[64*ALD], vl[64*ALD];

    const int tid  = threadIdx.x;
    const int lane = tid & 31;
    const int warp = tid >> 5;
    const int g    = lane >> 2;
    const int tig  = lane & 3;
    const int t0   = blockIdx.x * 128;
    const int h    = blockIdx.y;
    const int qb   = blockIdx.z;
    const int b    = qb & (BB - 1);

    // persistent Q fragments (scale folded at projection)
    uint32_t qfh[4][4], qfl[4][4];
    {
        const int qrow = qb*512 + t0 + warp*16 + g;
#pragma unroll
        for (int kc = 0; kc < 4; kc++) {
            int base = qrow*512 + h*64 + kc*16 + 2*tig;
            qfh[kc][0] = *(const uint32_t*)&g_qh[base];
            qfh[kc][1] = *(const uint32_t*)&g_qh[base + 8*512];
            qfh[kc][2] = *(const uint32_t*)&g_qh[base + 8];
            qfh[kc][3] = *(const uint32_t*)&g_qh[base + 8*512 + 8];
            qfl[kc][0] = *(const uint32_t*)&g_ql[base];
            qfl[kc][1] = *(const uint32_t*)&g_ql[base + 8*512];
            qfl[kc][2] = *(const uint32_t*)&g_ql[base + 8];
            qfl[kc][3] = *(const uint32_t*)&g_ql[base + 8*512 + 8];
        }
    }

    float of[8][4], oa[8][4];
    float m0 = -1e30f, m1 = -1e30f, l0 = 0.f, l1 = 0.f;
#pragma unroll
    for (int j = 0; j < 8; j++)
#pragma unroll
        for (int r = 0; r < 4; r++) { of[j][r] = 0.f; oa[j][r] = 0.f; }

    for (int c = 0; c < NVAR; c++) {
        const int ktok = (c*BB + b)*512;
        const int vrow = ((c*BB + b)*HH + h)*64;
        for (int s0 = 0; s0 < TT; s0 += 64) {
            __syncthreads();
            // stage K [s][dk] and V^T [dv][s] tiles, hi+lo
#pragma unroll
            for (int r = 0; r < 2; r++) {
                int idx = tid + r*256;          // 0..511
                int row = idx >> 3, seg = idx & 7;
                *(uint4*)&kh[row*ALD + seg*8] =
                    *(const uint4*)&g_kh[(ktok + s0 + row)*512 + h*64 + seg*8];
                *(uint4*)&kl[row*ALD + seg*8] =
                    *(const uint4*)&g_kl[(ktok + s0 + row)*512 + h*64 + seg*8];
                *(uint4*)&vh[row*ALD + seg*8] =
                    *(const uint4*)&g_vTh[(vrow + row)*512 + s0 + seg*8];
                *(uint4*)&vl[row*ALD + seg*8] =
                    *(const uint4*)&g_vTl[(vrow + row)*512 + s0 + seg*8];
            }
            __syncthreads();

            // S = Q@K^T (64x64 per warp-row-slice of 16)
            float sf[8][4];
#pragma unroll
            for (int j = 0; j < 8; j++)
#pragma unroll
                for (int r = 0; r < 4; r++) sf[j][r] = 0.f;
#pragma unroll
            for (int kc = 0; kc < 4; kc++) {
#pragma unroll
                for (int j = 0; j < 8; j++) {
                    const int ro = (j*8 + g)*ALD + kc*16 + 2*tig;
                    uint32_t bfr[2], bfl[2];
                    bfr[0] = *(const uint32_t*)&kh[ro];
                    bfr[1] = *(const uint32_t*)&kh[ro + 8];
                    bfl[0] = *(const uint32_t*)&kl[ro];
                    bfl[1] = *(const uint32_t*)&kl[ro + 8];
                    mma_bf16(sf[j], qfh[kc], bfr);
                    mma_bf16(sf[j], qfl[kc], bfr);
                    mma_bf16(sf[j], qfh[kc], bfl);
                }
            }

            // online softmax on fragments (rows g / g+8)
            float mx0 = -1e30f, mx1 = -1e30f;
#pragma unroll
            for (int j = 0; j < 8; j++) {
                mx0 = fmaxf(mx0, fmaxf(sf[j][0], sf[j][1]));
                mx1 = fmaxf(mx1, fmaxf(sf[j][2], sf[j][3]));
            }
            mx0 = fmaxf(mx0, __shfl_xor_sync(0xffffffffu, mx0, 1));
            mx0 = fmaxf(mx0, __shfl_xor_sync(0xffffffffu, mx0, 2));
            mx1 = fmaxf(mx1, __shfl_xor_sync(0xffffffffu, mx1, 1));
            mx1 = fmaxf(mx1, __shfl_xor_sync(0xffffffffu, mx1, 2));
            float mn0 = fmaxf(m0, mx0), mn1 = fmaxf(m1, mx1);
            float cr0 = __expf(m0 - mn0), cr1 = __expf(m1 - mn1);
            float rs0 = 0.f, rs1 = 0.f;
#pragma unroll
            for (int j = 0; j < 8; j++) {
                sf[j][0] = __expf(sf[j][0] - mn0);
                sf[j][1] = __expf(sf[j][1] - mn0);
                sf[j][2] = __expf(sf[j][2] - mn1);
                sf[j][3] = __expf(sf[j][3] - mn1);
                rs0 += sf[j][0] + sf[j][1];
                rs1 += sf[j][2] + sf[j][3];
            }
            rs0 += __shfl_xor_sync(0xffffffffu, rs0, 1);
            rs0 += __shfl_xor_sync(0xffffffffu, rs0, 2);
            rs1 += __shfl_xor_sync(0xffffffffu, rs1, 1);
            rs1 += __shfl_xor_sync(0xffffffffu, rs1, 2);
            l0 = l0*cr0 + rs0; m0 = mn0;
            l1 = l1*cr1 + rs1; m1 = mn1;
#pragma unroll
            for (int j = 0; j < 8; j++) {
                of[j][0] *= cr0; of[j][1] *= cr0;
                of[j][2] *= cr1; of[j][3] *= cr1;
            }

            // O += P@V  (P fragments built in registers from sf)
#pragma unroll
            for (int kc = 0; kc < 4; kc++) {
                uint32_t ph[4], pl[4];
                bsplit2(sf[2*kc  ][0], sf[2*kc  ][1], ph[0], pl[0]);
                bsplit2(sf[2*kc  ][2], sf[2*kc  ][3], ph[1], pl[1]);
                bsplit2(sf[2*kc+1][0], sf[2*kc+1][1], ph[2], pl[2]);
                bsplit2(sf[2*kc+1][2], sf[2*kc+1][3], ph[3], pl[3]);
#pragma unroll
                for (int j = 0; j < 8; j++) {
                    const int ro = (j*8 + g)*ALD + kc*16 + 2*tig;
                    uint32_t bfr[2], bfl[2];
                    bfr[0] = *(const uint32_t*)&vh[ro];
                    bfr[1] = *(const uint32_t*)&vh[ro + 8];
                    bfl[0] = *(const uint32_t*)&vl[ro];
                    bfl[1] = *(const uint32_t*)&vl[ro + 8];
                    mma_bf16(of[j], ph, bfr);
                    mma_bf16(of[j], pl, bfr);
                    mma_bf16(of[j], ph, bfl);
                }
            }
        }
        // fold this key-variable
        float i0 = 1.f / l0, i1 = 1.f / l1;
#pragma unroll
        for (int j = 0; j < 8; j++) {
            oa[j][0] += of[j][0]*i0; oa[j][1] += of[j][1]*i0;
            oa[j][2] += of[j][2]*i1; oa[j][3] += of[j][3]*i1;
            of[j][0] = of[j][1] = of[j][2] = of[j][3] = 0.f;
        }
        m0 = m1 = -1e30f; l0 = l1 = 0.f;
    }

    // write ctx_sum split
    const int orow = qb*512 + t0 + warp*16 + g;
#pragma unroll
    for (int j = 0; j < 8; j++) {
        int addr = orow*512 + h*64 + j*8 + 2*tig;
        uint32_t hb, lb;
        bsplit2(oa[j][0], oa[j][1], hb, lb);
        *(uint32_t*)&g_ctxh[addr] = hb;
        *(uint32_t*)&g_ctxl[addr] = lb;
        bsplit2(oa[j][2], oa[j][3], hb, lb);
        *(uint32_t*)&g_ctxh[addr + 8*512] = hb;
        *(uint32_t*)&g_ctxl[addr + 8*512] = lb;
    }
}

// ---------------------------------------------------------------------------
// LayerNorm: one block per row of 512
// ---------------------------------------------------------------------------
__global__ __launch_bounds__(128) void ln_kernel(const float* __restrict__ gamma,
                                                 const float* __restrict__ beta,
                                                 float* __restrict__ out)
{
    const int row = blockIdx.x;
    const int t = threadIdx.x;
    float4 v = *(const float4*)&g_res[row*512 + t*4];
    float s  = v.x + v.y + v.z + v.w;
    float ss = v.x*v.x + v.y*v.y + v.z*v.z + v.w*v.w;
#pragma unroll
    for (int off = 16; off; off >>= 1) {
        s  += __shfl_xor_sync(0xffffffffu, s, off);
        ss += __shfl_xor_sync(0xffffffffu, ss, off);
    }
    __shared__ float as[4], ass[4];
    if ((t & 31) == 0) { as[t >> 5] = s; ass[t >> 5] = ss; }
    __syncthreads();
    s  = as[0] + as[1] + as[2] + as[3];
    ss = ass[0] + ass[1] + ass[2] + ass[3];
    float mu  = s * (1.f / 512.f);
    float var = ss * (1.f / 512.f) - mu * mu;
    float inv = rsqrtf(var + 1e-5f);
    float4 gg = *(const float4*)&gamma[t*4];
    float4 bb = *(const float4*)&beta[t*4];
    float4 o4;
    o4.x = (v.x - mu)*inv*gg.x + bb.x;
    o4.y = (v.y - mu)*inv*gg.y + bb.y;
    o4.z = (v.z - mu)*inv*gg.z + bb.z;
    o4.w = (v.w - mu)*inv*gg.w + bb.w;
    *(float4*)&out[row*512 + t*4] = o4;
}

extern "C" void kernel_launch(void* const* d_in, const int* in_sizes, int n_in,
                              void* d_out, int out_size)
{
    const float* x     = (const float*)d_in[0];
    const float* bq    = (const float*)d_in[2];
    const float* bk    = (const float*)d_in[4];
    const float* bv    = (const float*)d_in[6];
    const float* bo    = (const float*)d_in[8];
    const float* gamma = (const float*)d_in[9];
    const float* beta  = (const float*)d_in[10];
    const float* Wq    = (const float*)d_in[1];
    const float* Wk    = (const float*)d_in[3];
    const float* Wv    = (const float*)d_in[5];
    const float* Wo    = (const float*)d_in[7];
    float* out = (float*)d_out;

    prep_x_kernel<<<MROWS*DD/4/256, 256>>>(x);
    prep_w_kernel<<<dim3(16, 16, 4), dim3(32, 8)>>>(Wq, Wk, Wv, Wo);
    hmma_qkv<<<dim3(512/64, MROWS/128, 3), 256>>>(bq, bk, bv);
    attn_mma_kernel<<<dim3(TT/128, HH, NVAR*BB), 256>>>();
    hmma_out<<<dim3(512/64, MROWS/128, 1), 256>>>(bo, x);
    ln_kernel<<<MROWS, 128>>>(gamma, beta, out);
}

// round 10
// speedup vs baseline: 2.4379x; 1.0759x over previous
#include <cuda_runtime.h>
#include <cuda_bf16.h>
#include <cstdint>
#include <math.h>

#define NVAR 4
#define BB   4
#define TT   512
#define DD   512
#define HH   8
#define MROWS (NVAR*BB*TT)   // 8192

// Scratch (alloc-free rule: __device__ globals)
__device__ float g_res[MROWS*DD];
__device__ __nv_bfloat16 g_xh[MROWS*DD],   g_xl[MROWS*DD];
__device__ __nv_bfloat16 g_qh[MROWS*DD],   g_ql[MROWS*DD];    // Q*0.125
__device__ __nv_bfloat16 g_kh[MROWS*DD],   g_kl[MROWS*DD];
__device__ __nv_bfloat16 g_vTh[MROWS*DD],  g_vTl[MROWS*DD];   // V^T
__device__ __nv_bfloat16 g_ctxh[MROWS*DD], g_ctxl[MROWS*DD];
__device__ __nv_bfloat16 g_wh[4*DD*DD],    g_wl[4*DD*DD];     // weights [w][n][k]

// ------------------------- helpers ----------------------------------------
__device__ __forceinline__ void mma_bf16(float* c, const uint32_t* a,
                                         const uint32_t* b) {
    asm volatile(
        "mma.sync.aligned.m16n8k16.row.col.f32.bf16.bf16.f32 "
        "{%0,%1,%2,%3}, {%4,%5,%6,%7}, {%8,%9}, {%0,%1,%2,%3};"
        : "+f"(c[0]), "+f"(c[1]), "+f"(c[2]), "+f"(c[3])
        : "r"(a[0]), "r"(a[1]), "r"(a[2]), "r"(a[3]), "r"(b[0]), "r"(b[1]));
}
__device__ __forceinline__ uint32_t cvt_bf2(float hi_v, float lo_v) {
    uint32_t r;
    asm("cvt.rn.bf16x2.f32 %0, %1, %2;" : "=r"(r) : "f"(hi_v), "f"(lo_v));
    return r;
}
__device__ __forceinline__ void bsplit2(float x0, float x1,
                                        uint32_t& h, uint32_t& l) {
    h = cvt_bf2(x1, x0);
    float h0 = __uint_as_float(h << 16);
    float h1 = __uint_as_float(h & 0xffff0000u);
    l = cvt_bf2(x1 - h1, x0 - h0);
}
__device__ __forceinline__ void split_store(__nv_bfloat16* H, __nv_bfloat16* L,
                                            int idx, const float* r) {
#pragma unroll
    for (int j = 0; j < 4; j += 2) {
        uint32_t h, l;
        bsplit2(r[j], r[j+1], h, l);
        *(uint32_t*)&H[idx + j] = h;
        *(uint32_t*)&L[idx + j] = l;
    }
}
__device__ __forceinline__ uint32_t smem_u32(const void* p) {
    uint32_t a;
    asm("{ .reg .u64 t; cvta.to.shared.u64 t, %1; cvt.u32.u64 %0, t; }"
        : "=r"(a) : "l"(p));
    return a;
}
__device__ __forceinline__ void cp16(uint32_t dst, const void* src) {
    asm volatile("cp.async.cg.shared.global [%0], [%1], 16;"
                 :: "r"(dst), "l"(src));
}
#define CP_COMMIT() asm volatile("cp.async.commit_group;" ::: "memory")
#define CP_WAIT(n)  asm volatile("cp.async.wait_group %0;" :: "n"(n) : "memory")

// ---------------------------------------------------------------------------
// prep kernels
// ---------------------------------------------------------------------------
__global__ __launch_bounds__(256) void prep_x_kernel(const float* __restrict__ x) {
    int i4 = blockIdx.x * blockDim.x + threadIdx.x;
    float4 v = *(const float4*)&x[i4 * 4];
    float r[4] = {v.x, v.y, v.z, v.w};
    split_store(g_xh, g_xl, i4 * 4, r);
}

__global__ __launch_bounds__(256) void prep_w_kernel(
    const float* __restrict__ Wq, const float* __restrict__ Wk,
    const float* __restrict__ Wv, const float* __restrict__ Wo)
{
    __shared__ float tile[32][33];
    const int w = blockIdx.z;
    const float* W = (w == 0) ? Wq : (w == 1) ? Wk : (w == 2) ? Wv : Wo;
    const int k0 = blockIdx.x * 32, n0 = blockIdx.y * 32;
    const int tx = threadIdx.x, ty = threadIdx.y;
#pragma unroll
    for (int i = 0; i < 32; i += 8)
        tile[ty + i][tx] = W[(k0 + ty + i) * 512 + n0 + tx];
    __syncthreads();
    __nv_bfloat16* H = g_wh + w * DD * DD;
    __nv_bfloat16* L = g_wl + w * DD * DD;
#pragma unroll
    for (int i = 0; i < 32; i += 8) {
        float v = tile[tx][ty + i];
        __nv_bfloat16 h = __float2bfloat16_rn(v);
        __nv_bfloat16 l = __float2bfloat16_rn(v - __bfloat162float(h));
        int idx = (n0 + ty + i) * 512 + k0 + tx;
        H[idx] = h; L[idx] = l;
    }
}

// ---------------------------------------------------------------------------
// HMMA bf16-split GEMM, cp.async double-buffered.
// 128x64 tile, 8 warps (4M x 2N), warp tile 32x32.
// ---------------------------------------------------------------------------
#define LDK 40
#define GA_SZ (128*LDK*2)          // 10240 B per A array
#define GB_SZ (64*LDK*2)           // 5120 B per B array
#define GSTAGE (2*GA_SZ + 2*GB_SZ) // 30720 B
#define GSMEM (2*GSTAGE)           // 61440 B

__device__ __forceinline__ void hmma_gemm_body(
    const __nv_bfloat16* __restrict__ Ah, const __nv_bfloat16* __restrict__ Al,
    const __nv_bfloat16* __restrict__ Wh, const __nv_bfloat16* __restrict__ Wl,
    const float* __restrict__ bias, const float* __restrict__ resid,
    float scale, int mode, float* __restrict__ C,
    __nv_bfloat16* __restrict__ Hd, __nv_bfloat16* __restrict__ Ld)
{
    extern __shared__ char gsm[];
    const uint32_t smb = smem_u32(gsm);

    const int tid = threadIdx.x;
    const int lane = tid & 31;
    const int warp = tid >> 5;
    const int warpM = warp >> 1;
    const int warpN = warp & 1;
    const int g   = lane >> 2;
    const int tig = lane & 3;
    const int bm0 = blockIdx.y * 128;
    const int bn0 = blockIdx.x * 64;

    // fixed per-thread copy coords
    const int ar0 = (tid*2) >> 2,     as0 = (tid*2) & 3;
    const int ar1 = (tid*2+1) >> 2,   as1 = (tid*2+1) & 3;
    const int br  = tid >> 2,         bs  = tid & 3;

    float acc[2][4][4];
#pragma unroll
    for (int mt = 0; mt < 2; mt++)
#pragma unroll
        for (int nt = 0; nt < 4; nt++)
#pragma unroll
            for (int r = 0; r < 4; r++) acc[mt][nt][r] = 0.f;

#define G_ISSUE(k0, st) do {                                                  \
    uint32_t b0 = smb + (st)*GSTAGE;                                          \
    cp16(b0 + (ar0*LDK + as0*8)*2,          &Ah[(bm0+ar0)*512 + (k0) + as0*8]); \
    cp16(b0 + (ar1*LDK + as1*8)*2,          &Ah[(bm0+ar1)*512 + (k0) + as1*8]); \
    cp16(b0 + GA_SZ + (ar0*LDK + as0*8)*2,  &Al[(bm0+ar0)*512 + (k0) + as0*8]); \
    cp16(b0 + GA_SZ + (ar1*LDK + as1*8)*2,  &Al[(bm0+ar1)*512 + (k0) + as1*8]); \
    cp16(b0 + 2*GA_SZ + (br*LDK + bs*8)*2,        &Wh[(bn0+br)*512 + (k0) + bs*8]); \
    cp16(b0 + 2*GA_SZ + GB_SZ + (br*LDK + bs*8)*2,&Wl[(bn0+br)*512 + (k0) + bs*8]); \
} while (0)

    G_ISSUE(0, 0); CP_COMMIT();

    for (int it = 0; it < 16; it++) {
        if (it + 1 < 16) { G_ISSUE((it+1)*32, (it+1)&1); CP_COMMIT(); CP_WAIT(1); }
        else CP_WAIT(0);
        __syncthreads();

        const char* st = gsm + (it & 1)*GSTAGE;
        const __nv_bfloat16* sAh = (const __nv_bfloat16*)st;
        const __nv_bfloat16* sAl = (const __nv_bfloat16*)(st + GA_SZ);
        const __nv_bfloat16* sBh = (const __nv_bfloat16*)(st + 2*GA_SZ);
        const __nv_bfloat16* sBl = (const __nv_bfloat16*)(st + 2*GA_SZ + GB_SZ);

#pragma unroll
        for (int kk = 0; kk < 32; kk += 16) {
            uint32_t ah[2][4], al[2][4];
#pragma unroll
            for (int mt = 0; mt < 2; mt++) {
                int rb = warpM*32 + mt*16;
                int ka = kk + 2*tig;
                ah[mt][0] = *(const uint32_t*)&sAh[(rb + g    )*LDK + ka];
                ah[mt][1] = *(const uint32_t*)&sAh[(rb + g + 8)*LDK + ka];
                ah[mt][2] = *(const uint32_t*)&sAh[(rb + g    )*LDK + ka + 8];
                ah[mt][3] = *(const uint32_t*)&sAh[(rb + g + 8)*LDK + ka + 8];
                al[mt][0] = *(const uint32_t*)&sAl[(rb + g    )*LDK + ka];
                al[mt][1] = *(const uint32_t*)&sAl[(rb + g + 8)*LDK + ka];
                al[mt][2] = *(const uint32_t*)&sAl[(rb + g    )*LDK + ka + 8];
                al[mt][3] = *(const uint32_t*)&sAl[(rb + g + 8)*LDK + ka + 8];
            }
            uint32_t bh[4][2], bl[4][2];
#pragma unroll
            for (int nt = 0; nt < 4; nt++) {
                int n = warpN*32 + nt*8 + g;
                int kb = kk + 2*tig;
                bh[nt][0] = *(const uint32_t*)&sBh[n*LDK + kb];
                bh[nt][1] = *(const uint32_t*)&sBh[n*LDK + kb + 8];
                bl[nt][0] = *(const uint32_t*)&sBl[n*LDK + kb];
                bl[nt][1] = *(const uint32_t*)&sBl[n*LDK + kb + 8];
            }
#pragma unroll
            for (int mt = 0; mt < 2; mt++)
#pragma unroll
                for (int nt = 0; nt < 4; nt++) {
                    mma_bf16(acc[mt][nt], ah[mt], bh[nt]);
                    mma_bf16(acc[mt][nt], ah[mt], bl[nt]);
                    mma_bf16(acc[mt][nt], al[mt], bh[nt]);
                }
        }
        __syncthreads();
    }

#pragma unroll
    for (int mt = 0; mt < 2; mt++)
#pragma unroll
        for (int nt = 0; nt < 4; nt++) {
            const float* ac = acc[mt][nt];
            int r0 = bm0 + warpM*32 + mt*16 + g;
            int cc = bn0 + warpN*32 + nt*8 + 2*tig;
            float2 bb = *(const float2*)&bias[cc];
            if (mode == 0) {
                float2 o0, o1;
                o0.x = ac[0]*scale + bb.x;  o0.y = ac[1]*scale + bb.y;
                o1.x = ac[2]*scale + bb.x;  o1.y = ac[3]*scale + bb.y;
                float2 q0 = *(const float2*)&resid[r0*512 + cc];
                float2 q1 = *(const float2*)&resid[(r0+8)*512 + cc];
                o0.x += q0.x; o0.y += q0.y;
                o1.x += q1.x; o1.y += q1.y;
                *(float2*)&C[r0*512 + cc]     = o0;
                *(float2*)&C[(r0+8)*512 + cc] = o1;
            } else if (mode == 1) {
                uint32_t h, l;
                bsplit2((ac[0] + bb.x)*scale, (ac[1] + bb.y)*scale, h, l);
                *(uint32_t*)&Hd[r0*512 + cc] = h;
                *(uint32_t*)&Ld[r0*512 + cc] = l;
                bsplit2((ac[2] + bb.x)*scale, (ac[3] + bb.y)*scale, h, l);
                *(uint32_t*)&Hd[(r0+8)*512 + cc] = h;
                *(uint32_t*)&Ld[(r0+8)*512 + cc] = l;
            } else {
#pragma unroll
                for (int e = 0; e < 4; e++) {
                    int r  = (e < 2) ? r0 : r0 + 8;
                    int cx = cc + (e & 1);
                    float o = ac[e] + ((e & 1) ? bb.y : bb.x);
                    int cb = r >> 9, t = r & 511;
                    int hh = cx >> 6, dv = cx & 63;
                    int addr = (((cb*8 + hh)*64) + dv)*512 + t;
                    __nv_bfloat16 bh16 = __float2bfloat16_rn(o);
                    __nv_bfloat16 bl16 =
                        __float2bfloat16_rn(o - __bfloat162float(bh16));
                    Hd[addr] = bh16; Ld[addr] = bl16;
                }
            }
        }
}

__global__ __launch_bounds__(256) void hmma_qkv(
    const float* __restrict__ bq, const float* __restrict__ bk,
    const float* __restrict__ bv)
{
    int w = blockIdx.z;
    if (w == 0)
        hmma_gemm_body(g_xh, g_xl, g_wh, g_wl, bq, nullptr,
                       0.125f, 1, nullptr, g_qh, g_ql);
    else if (w == 1)
        hmma_gemm_body(g_xh, g_xl, g_wh + DD*DD, g_wl + DD*DD, bk, nullptr,
                       1.0f, 1, nullptr, g_kh, g_kl);
    else
        hmma_gemm_body(g_xh, g_xl, g_wh + 2*DD*DD, g_wl + 2*DD*DD, bv, nullptr,
                       1.0f, 2, nullptr, g_vTh, g_vTl);
}

__global__ __launch_bounds__(256) void hmma_out(
    const float* __restrict__ bo, const float* __restrict__ x)
{
    hmma_gemm_body(g_ctxh, g_ctxl, g_wh + 3*DD*DD, g_wl + 3*DD*DD,
                   bo, x, 1.0f / (float)NVAR, 0, g_res, nullptr, nullptr);
}

// ---------------------------------------------------------------------------
// FA2-style mma.sync attention with cp.async double-buffered K/V staging.
// Block = 256 thr (8 warps), 128 Q rows, one (qb, h).
// ---------------------------------------------------------------------------
#define ALD 72
#define KSZ (64*ALD*2)         // 9216 B per array
#define ASTAGE (4*KSZ)         // 36864 B
#define ASMEM (2*ASTAGE)       // 73728 B

__global__ __launch_bounds__(256) void attn_mma_kernel()
{
    extern __shared__ char asm_sm[];
    const uint32_t smb = smem_u32(asm_sm);

    const int tid  = threadIdx.x;
    const int lane = tid & 31;
    const int warp = tid >> 5;
    const int g    = lane >> 2;
    const int tig  = lane & 3;
    const int t0   = blockIdx.x * 128;
    const int h    = blockIdx.y;
    const int qb   = blockIdx.z;
    const int b    = qb & (BB - 1);

    // persistent Q fragments
    uint32_t qfh[4][4], qfl[4][4];
    {
        const int qrow = qb*512 + t0 + warp*16 + g;
#pragma unroll
        for (int kc = 0; kc < 4; kc++) {
            int base = qrow*512 + h*64 + kc*16 + 2*tig;
            qfh[kc][0] = *(const uint32_t*)&g_qh[base];
            qfh[kc][1] = *(const uint32_t*)&g_qh[base + 8*512];
            qfh[kc][2] = *(const uint32_t*)&g_qh[base + 8];
            qfh[kc][3] = *(const uint32_t*)&g_qh[base + 8*512 + 8];
            qfl[kc][0] = *(const uint32_t*)&g_ql[base];
            qfl[kc][1] = *(const uint32_t*)&g_ql[base + 8*512];
            qfl[kc][2] = *(const uint32_t*)&g_ql[base + 8];
            qfl[kc][3] = *(const uint32_t*)&g_ql[base + 8*512 + 8];
        }
    }

    // per-thread copy coords (2 chunks of 16B per array)
    const int cr0 = tid >> 3,           cs0 = tid & 7;
    const int cr1 = (tid + 256) >> 3,   cs1 = (tid + 256) & 7;

#define A_ISSUE(ti, st) do {                                                  \
    int c_ = (ti) >> 3, s0_ = ((ti) & 7) * 64;                                \
    int kt_ = (c_*BB + b)*512;                                                \
    int vr_ = ((c_*BB + b)*HH + h)*64;                                        \
    uint32_t b0 = smb + (st)*ASTAGE;                                          \
    uint32_t o0 = (cr0*ALD + cs0*8)*2, o1 = (cr1*ALD + cs1*8)*2;              \
    cp16(b0 + o0,         &g_kh [(kt_ + s0_ + cr0)*512 + h*64 + cs0*8]);      \
    cp16(b0 + o1,         &g_kh [(kt_ + s0_ + cr1)*512 + h*64 + cs1*8]);      \
    cp16(b0 + KSZ + o0,   &g_kl [(kt_ + s0_ + cr0)*512 + h*64 + cs0*8]);      \
    cp16(b0 + KSZ + o1,   &g_kl [(kt_ + s0_ + cr1)*512 + h*64 + cs1*8]);      \
    cp16(b0 + 2*KSZ + o0, &g_vTh[(vr_ + cr0)*512 + s0_ + cs0*8]);             \
    cp16(b0 + 2*KSZ + o1, &g_vTh[(vr_ + cr1)*512 + s0_ + cs1*8]);             \
    cp16(b0 + 3*KSZ + o0, &g_vTl[(vr_ + cr0)*512 + s0_ + cs0*8]);             \
    cp16(b0 + 3*KSZ + o1, &g_vTl[(vr_ + cr1)*512 + s0_ + cs1*8]);             \
} while (0)

    float of[8][4], oa[8][4];
    float m0 = -1e30f, m1 = -1e30f, l0 = 0.f, l1 = 0.f;
#pragma unroll
    for (int j = 0; j < 8; j++)
#pragma unroll
        for (int r = 0; r < 4; r++) { of[j][r] = 0.f; oa[j][r] = 0.f; }

    A_ISSUE(0, 0); CP_COMMIT();

    for (int ti = 0; ti < 32; ti++) {
        if (ti + 1 < 32) { A_ISSUE(ti+1, (ti+1)&1); CP_COMMIT(); CP_WAIT(1); }
        else CP_WAIT(0);
        __syncthreads();

        const char* st = asm_sm + (ti & 1)*ASTAGE;
        const __nv_bfloat16* kh = (const __nv_bfloat16*)st;
        const __nv_bfloat16* kl = (const __nv_bfloat16*)(st + KSZ);
        const __nv_bfloat16* vh = (const __nv_bfloat16*)(st + 2*KSZ);
        const __nv_bfloat16* vl = (const __nv_bfloat16*)(st + 3*KSZ);

        // S = Q@K^T
        float sf[8][4];
#pragma unroll
        for (int j = 0; j < 8; j++)
#pragma unroll
            for (int r = 0; r < 4; r++) sf[j][r] = 0.f;
#pragma unroll
        for (int kc = 0; kc < 4; kc++) {
#pragma unroll
            for (int j = 0; j < 8; j++) {
                const int ro = (j*8 + g)*ALD + kc*16 + 2*tig;
                uint32_t bfr[2], bfl[2];
                bfr[0] = *(const uint32_t*)&kh[ro];
                bfr[1] = *(const uint32_t*)&kh[ro + 8];
                bfl[0] = *(const uint32_t*)&kl[ro];
                bfl[1] = *(const uint32_t*)&kl[ro + 8];
                mma_bf16(sf[j], qfh[kc], bfr);
                mma_bf16(sf[j], qfl[kc], bfr);
                mma_bf16(sf[j], qfh[kc], bfl);
            }
        }

        // online softmax
        float mx0 = -1e30f, mx1 = -1e30f;
#pragma unroll
        for (int j = 0; j < 8; j++) {
            mx0 = fmaxf(mx0, fmaxf(sf[j][0], sf[j][1]));
            mx1 = fmaxf(mx1, fmaxf(sf[j][2], sf[j][3]));
        }
        mx0 = fmaxf(mx0, __shfl_xor_sync(0xffffffffu, mx0, 1));
        mx0 = fmaxf(mx0, __shfl_xor_sync(0xffffffffu, mx0, 2));
        mx1 = fmaxf(mx1, __shfl_xor_sync(0xffffffffu, mx1, 1));
        mx1 = fmaxf(mx1, __shfl_xor_sync(0xffffffffu, mx1, 2));
        float mn0 = fmaxf(m0, mx0), mn1 = fmaxf(m1, mx1);
        float cr_0 = __expf(m0 - mn0), cr_1 = __expf(m1 - mn1);
        float rs0 = 0.f, rs1 = 0.f;
#pragma unroll
        for (int j = 0; j < 8; j++) {
            sf[j][0] = __expf(sf[j][0] - mn0);
            sf[j][1] = __expf(sf[j][1] - mn0);
            sf[j][2] = __expf(sf[j][2] - mn1);
            sf[j][3] = __expf(sf[j][3] - mn1);
            rs0 += sf[j][0] + sf[j][1];
            rs1 += sf[j][2] + sf[j][3];
        }
        rs0 += __shfl_xor_sync(0xffffffffu, rs0, 1);
        rs0 += __shfl_xor_sync(0xffffffffu, rs0, 2);
        rs1 += __shfl_xor_sync(0xffffffffu, rs1, 1);
        rs1 += __shfl_xor_sync(0xffffffffu, rs1, 2);
        l0 = l0*cr_0 + rs0; m0 = mn0;
        l1 = l1*cr_1 + rs1; m1 = mn1;
#pragma unroll
        for (int j = 0; j < 8; j++) {
            of[j][0] *= cr_0; of[j][1] *= cr_0;
            of[j][2] *= cr_1; of[j][3] *= cr_1;
        }

        // O += P@V
#pragma unroll
        for (int kc = 0; kc < 4; kc++) {
            uint32_t ph[4], pl[4];
            bsplit2(sf[2*kc  ][0], sf[2*kc  ][1], ph[0], pl[0]);
            bsplit2(sf[2*kc  ][2], sf[2*kc  ][3], ph[1], pl[1]);
            bsplit2(sf[2*kc+1][0], sf[2*kc+1][1], ph[2], pl[2]);
            bsplit2(sf[2*kc+1][2], sf[2*kc+1][3], ph[3], pl[3]);
#pragma unroll
            for (int j = 0; j < 8; j++) {
                const int ro = (j*8 + g)*ALD + kc*16 + 2*tig;
                uint32_t bfr[2], bfl[2];
                bfr[0] = *(const uint32_t*)&vh[ro];
                bfr[1] = *(const uint32_t*)&vh[ro + 8];
                bfl[0] = *(const uint32_t*)&vl[ro];
                bfl[1] = *(const uint32_t*)&vl[ro + 8];
                mma_bf16(of[j], ph, bfr);
                mma_bf16(of[j], pl, bfr);
                mma_bf16(of[j], ph, bfl);
            }
        }

        if ((ti & 7) == 7) {   // fold this key-variable
            float i0 = 1.f / l0, i1 = 1.f / l1;
#pragma unroll
            for (int j = 0; j < 8; j++) {
                oa[j][0] += of[j][0]*i0; oa[j][1] += of[j][1]*i0;
                oa[j][2] += of[j][2]*i1; oa[j][3] += of[j][3]*i1;
                of[j][0] = of[j][1] = of[j][2] = of[j][3] = 0.f;
            }
            m0 = m1 = -1e30f; l0 = l1 = 0.f;
        }
        __syncthreads();
    }

    // write ctx_sum split
    const int orow = qb*512 + t0 + warp*16 + g;
#pragma unroll
    for (int j = 0; j < 8; j++) {
        int addr = orow*512 + h*64 + j*8 + 2*tig;
        uint32_t hb, lb;
        bsplit2(oa[j][0], oa[j][1], hb, lb);
        *(uint32_t*)&g_ctxh[addr] = hb;
        *(uint32_t*)&g_ctxl[addr] = lb;
        bsplit2(oa[j][2], oa[j][3], hb, lb);
        *(uint32_t*)&g_ctxh[addr + 8*512] = hb;
        *(uint32_t*)&g_ctxl[addr + 8*512] = lb;
    }
}

// ---------------------------------------------------------------------------
// LayerNorm
// ---------------------------------------------------------------------------
__global__ __launch_bounds__(128) void ln_kernel(const float* __restrict__ gamma,
                                                 const float* __restrict__ beta,
                                                 float* __restrict__ out)
{
    const int row = blockIdx.x;
    const int t = threadIdx.x;
    float4 v = *(const float4*)&g_res[row*512 + t*4];
    float s  = v.x + v.y + v.z + v.w;
    float ss = v.x*v.x + v.y*v.y + v.z*v.z + v.w*v.w;
#pragma unroll
    for (int off = 16; off; off >>= 1) {
        s  += __shfl_xor_sync(0xffffffffu, s, off);
        ss += __shfl_xor_sync(0xffffffffu, ss, off);
    }
    __shared__ float as[4], ass[4];
    if ((t & 31) == 0) { as[t >> 5] = s; ass[t >> 5] = ss; }
    __syncthreads();
    s  = as[0] + as[1] + as[2] + as[3];
    ss = ass[0] + ass[1] + ass[2] + ass[3];
    float mu  = s * (1.f / 512.f);
    float var = ss * (1.f / 512.f) - mu * mu;
    float inv = rsqrtf(var + 1e-5f);
    float4 gg = *(const float4*)&gamma[t*4];
    float4 bb = *(const float4*)&beta[t*4];
    float4 o4;
    o4.x = (v.x - mu)*inv*gg.x + bb.x;
    o4.y = (v.y - mu)*inv*gg.y + bb.y;
    o4.z = (v.z - mu)*inv*gg.z + bb.z;
    o4.w = (v.w - mu)*inv*gg.w + bb.w;
    *(float4*)&out[row*512 + t*4] = o4;
}

extern "C" void kernel_launch(void* const* d_in, const int* in_sizes, int n_in,
                              void* d_out, int out_size)
{
    const float* x     = (const float*)d_in[0];
    const float* Wq    = (const float*)d_in[1];
    const float* bq    = (const float*)d_in[2];
    const float* Wk    = (const float*)d_in[3];
    const float* bk    = (const float*)d_in[4];
    const float* Wv    = (const float*)d_in[5];
    const float* bv    = (const float*)d_in[6];
    const float* Wo    = (const float*)d_in[7];
    const float* bo    = (const float*)d_in[8];
    const float* gamma = (const float*)d_in[9];
    const float* beta  = (const float*)d_in[10];
    float* out = (float*)d_out;

    cudaFuncSetAttribute(attn_mma_kernel,
                         cudaFuncAttributeMaxDynamicSharedMemorySize, ASMEM);
    cudaFuncSetAttribute(hmma_qkv,
                         cudaFuncAttributeMaxDynamicSharedMemorySize, GSMEM);
    cudaFuncSetAttribute(hmma_out,
                         cudaFuncAttributeMaxDynamicSharedMemorySize, GSMEM);

    prep_x_kernel<<<MROWS*DD/4/256, 256>>>(x);
    prep_w_kernel<<<dim3(16, 16, 4), dim3(32, 8)>>>(Wq, Wk, Wv, Wo);
    hmma_qkv<<<dim3(512/64, MROWS/128, 3), 256, GSMEM>>>(bq, bk, bv);
    attn_mma_kernel<<<dim3(TT/128, HH, NVAR*BB), 256, ASMEM>>>();
    hmma_out<<<dim3(512/64, MROWS/128, 1), 256, GSMEM>>>(bo, x);
    ln_kernel<<<MROWS, 128>>>(gamma, beta, out);
}

// round 11
// speedup vs baseline: 2.5651x; 1.0522x over previous
#include <cuda_runtime.h>
#include <cuda_bf16.h>
#include <cstdint>
#include <math.h>

#define NVAR 4
#define BB   4
#define TT   512
#define DD   512
#define HH   8
#define MROWS (NVAR*BB*TT)   // 8192

// Scratch (alloc-free rule: __device__ globals)
__device__ float g_res[MROWS*DD];
__device__ __nv_bfloat16 g_xh[MROWS*DD],   g_xl[MROWS*DD];
__device__ __nv_bfloat16 g_qh[MROWS*DD],   g_ql[MROWS*DD];    // Q*0.125
__device__ __nv_bfloat16 g_kh[MROWS*DD],   g_kl[MROWS*DD];
__device__ __nv_bfloat16 g_vTh[MROWS*DD],  g_vTl[MROWS*DD];   // V^T
__device__ __nv_bfloat16 g_ctxh[MROWS*DD], g_ctxl[MROWS*DD];
__device__ __nv_bfloat16 g_wh[4*DD*DD],    g_wl[4*DD*DD];     // weights [w][n][k]

// ------------------------- helpers ----------------------------------------
__device__ __forceinline__ void mma_bf16(float* c, const uint32_t* a,
                                         const uint32_t* b) {
    asm volatile(
        "mma.sync.aligned.m16n8k16.row.col.f32.bf16.bf16.f32 "
        "{%0,%1,%2,%3}, {%4,%5,%6,%7}, {%8,%9}, {%0,%1,%2,%3};"
        : "+f"(c[0]), "+f"(c[1]), "+f"(c[2]), "+f"(c[3])
        : "r"(a[0]), "r"(a[1]), "r"(a[2]), "r"(a[3]), "r"(b[0]), "r"(b[1]));
}
__device__ __forceinline__ uint32_t cvt_bf2(float hi_v, float lo_v) {
    uint32_t r;
    asm("cvt.rn.bf16x2.f32 %0, %1, %2;" : "=r"(r) : "f"(hi_v), "f"(lo_v));
    return r;
}
__device__ __forceinline__ void bsplit2(float x0, float x1,
                                        uint32_t& h, uint32_t& l) {
    h = cvt_bf2(x1, x0);
    float h0 = __uint_as_float(h << 16);
    float h1 = __uint_as_float(h & 0xffff0000u);
    l = cvt_bf2(x1 - h1, x0 - h0);
}
__device__ __forceinline__ void split_store(__nv_bfloat16* H, __nv_bfloat16* L,
                                            int idx, const float* r) {
#pragma unroll
    for (int j = 0; j < 4; j += 2) {
        uint32_t h, l;
        bsplit2(r[j], r[j+1], h, l);
        *(uint32_t*)&H[idx + j] = h;
        *(uint32_t*)&L[idx + j] = l;
    }
}
__device__ __forceinline__ uint32_t smem_u32(const void* p) {
    uint32_t a;
    asm("{ .reg .u64 t; cvta.to.shared.u64 t, %1; cvt.u32.u64 %0, t; }"
        : "=r"(a) : "l"(p));
    return a;
}
__device__ __forceinline__ void cp16(uint32_t dst, const void* src) {
    asm volatile("cp.async.cg.shared.global [%0], [%1], 16;"
                 :: "r"(dst), "l"(src));
}
#define CP_COMMIT() asm volatile("cp.async.commit_group;" ::: "memory")
#define CP_WAIT(n)  asm volatile("cp.async.wait_group %0;" :: "n"(n) : "memory")

// ---------------------------------------------------------------------------
// prep kernels
// ---------------------------------------------------------------------------
__global__ __launch_bounds__(256) void prep_x_kernel(const float* __restrict__ x) {
    int i4 = blockIdx.x * blockDim.x + threadIdx.x;
    float4 v = *(const float4*)&x[i4 * 4];
    float r[4] = {v.x, v.y, v.z, v.w};
    split_store(g_xh, g_xl, i4 * 4, r);
}

__global__ __launch_bounds__(256) void prep_w_kernel(
    const float* __restrict__ Wq, const float* __restrict__ Wk,
    const float* __restrict__ Wv, const float* __restrict__ Wo)
{
    __shared__ float tile[32][33];
    const int w = blockIdx.z;
    const float* W = (w == 0) ? Wq : (w == 1) ? Wk : (w == 2) ? Wv : Wo;
    const int k0 = blockIdx.x * 32, n0 = blockIdx.y * 32;
    const int tx = threadIdx.x, ty = threadIdx.y;
#pragma unroll
    for (int i = 0; i < 32; i += 8)
        tile[ty + i][tx] = W[(k0 + ty + i) * 512 + n0 + tx];
    __syncthreads();
    __nv_bfloat16* H = g_wh + w * DD * DD;
    __nv_bfloat16* L = g_wl + w * DD * DD;
#pragma unroll
    for (int i = 0; i < 32; i += 8) {
        float v = tile[tx][ty + i];
        __nv_bfloat16 h = __float2bfloat16_rn(v);
        __nv_bfloat16 l = __float2bfloat16_rn(v - __bfloat162float(h));
        int idx = (n0 + ty + i) * 512 + k0 + tx;
        H[idx] = h; L[idx] = l;
    }
}

// ---------------------------------------------------------------------------
// HMMA bf16-split GEMM, cp.async double-buffered.
// 128x64 tile, 8 warps (4M x 2N), warp tile 32x32.
// ---------------------------------------------------------------------------
#define LDK 40
#define GA_SZ (128*LDK*2)          // 10240 B per A array
#define GB_SZ (64*LDK*2)           // 5120 B per B array
#define GSTAGE (2*GA_SZ + 2*GB_SZ) // 30720 B
#define GSMEM (2*GSTAGE)           // 61440 B

__device__ __forceinline__ void hmma_gemm_body(
    const __nv_bfloat16* __restrict__ Ah, const __nv_bfloat16* __restrict__ Al,
    const __nv_bfloat16* __restrict__ Wh, const __nv_bfloat16* __restrict__ Wl,
    const float* __restrict__ bias, const float* __restrict__ resid,
    float scale, int mode, float* __restrict__ C,
    __nv_bfloat16* __restrict__ Hd, __nv_bfloat16* __restrict__ Ld)
{
    extern __shared__ char gsm[];
    const uint32_t smb = smem_u32(gsm);

    const int tid = threadIdx.x;
    const int lane = tid & 31;
    const int warp = tid >> 5;
    const int warpM = warp >> 1;
    const int warpN = warp & 1;
    const int g   = lane >> 2;
    const int tig = lane & 3;
    const int bm0 = blockIdx.y * 128;
    const int bn0 = blockIdx.x * 64;

    const int ar0 = (tid*2) >> 2,     as0 = (tid*2) & 3;
    const int ar1 = (tid*2+1) >> 2,   as1 = (tid*2+1) & 3;
    const int br  = tid >> 2,         bs  = tid & 3;

    float acc[2][4][4];
#pragma unroll
    for (int mt = 0; mt < 2; mt++)
#pragma unroll
        for (int nt = 0; nt < 4; nt++)
#pragma unroll
            for (int r = 0; r < 4; r++) acc[mt][nt][r] = 0.f;

#define G_ISSUE(k0, st) do {                                                  \
    uint32_t b0 = smb + (st)*GSTAGE;                                          \
    cp16(b0 + (ar0*LDK + as0*8)*2,          &Ah[(bm0+ar0)*512 + (k0) + as0*8]); \
    cp16(b0 + (ar1*LDK + as1*8)*2,          &Ah[(bm0+ar1)*512 + (k0) + as1*8]); \
    cp16(b0 + GA_SZ + (ar0*LDK + as0*8)*2,  &Al[(bm0+ar0)*512 + (k0) + as0*8]); \
    cp16(b0 + GA_SZ + (ar1*LDK + as1*8)*2,  &Al[(bm0+ar1)*512 + (k0) + as1*8]); \
    cp16(b0 + 2*GA_SZ + (br*LDK + bs*8)*2,        &Wh[(bn0+br)*512 + (k0) + bs*8]); \
    cp16(b0 + 2*GA_SZ + GB_SZ + (br*LDK + bs*8)*2,&Wl[(bn0+br)*512 + (k0) + bs*8]); \
} while (0)

    G_ISSUE(0, 0); CP_COMMIT();

    for (int it = 0; it < 16; it++) {
        if (it + 1 < 16) { G_ISSUE((it+1)*32, (it+1)&1); CP_COMMIT(); CP_WAIT(1); }
        else CP_WAIT(0);
        __syncthreads();

        const char* st = gsm + (it & 1)*GSTAGE;
        const __nv_bfloat16* sAh = (const __nv_bfloat16*)st;
        const __nv_bfloat16* sAl = (const __nv_bfloat16*)(st + GA_SZ);
        const __nv_bfloat16* sBh = (const __nv_bfloat16*)(st + 2*GA_SZ);
        const __nv_bfloat16* sBl = (const __nv_bfloat16*)(st + 2*GA_SZ + GB_SZ);

#pragma unroll
        for (int kk = 0; kk < 32; kk += 16) {
            uint32_t ah[2][4], al[2][4];
#pragma unroll
            for (int mt = 0; mt < 2; mt++) {
                int rb = warpM*32 + mt*16;
                int ka = kk + 2*tig;
                ah[mt][0] = *(const uint32_t*)&sAh[(rb + g    )*LDK + ka];
                ah[mt][1] = *(const uint32_t*)&sAh[(rb + g + 8)*LDK + ka];
                ah[mt][2] = *(const uint32_t*)&sAh[(rb + g    )*LDK + ka + 8];
                ah[mt][3] = *(const uint32_t*)&sAh[(rb + g + 8)*LDK + ka + 8];
                al[mt][0] = *(const uint32_t*)&sAl[(rb + g    )*LDK + ka];
                al[mt][1] = *(const uint32_t*)&sAl[(rb + g + 8)*LDK + ka];
                al[mt][2] = *(const uint32_t*)&sAl[(rb + g    )*LDK + ka + 8];
                al[mt][3] = *(const uint32_t*)&sAl[(rb + g + 8)*LDK + ka + 8];
            }
            uint32_t bh[4][2], bl[4][2];
#pragma unroll
            for (int nt = 0; nt < 4; nt++) {
                int n = warpN*32 + nt*8 + g;
                int kb = kk + 2*tig;
                bh[nt][0] = *(const uint32_t*)&sBh[n*LDK + kb];
                bh[nt][1] = *(const uint32_t*)&sBh[n*LDK + kb + 8];
                bl[nt][0] = *(const uint32_t*)&sBl[n*LDK + kb];
                bl[nt][1] = *(const uint32_t*)&sBl[n*LDK + kb + 8];
            }
#pragma unroll
            for (int mt = 0; mt < 2; mt++)
#pragma unroll
                for (int nt = 0; nt < 4; nt++) {
                    mma_bf16(acc[mt][nt], ah[mt], bh[nt]);
                    mma_bf16(acc[mt][nt], ah[mt], bl[nt]);
                    mma_bf16(acc[mt][nt], al[mt], bh[nt]);
                }
        }
        __syncthreads();
    }

#pragma unroll
    for (int mt = 0; mt < 2; mt++)
#pragma unroll
        for (int nt = 0; nt < 4; nt++) {
            const float* ac = acc[mt][nt];
            int r0 = bm0 + warpM*32 + mt*16 + g;
            int cc = bn0 + warpN*32 + nt*8 + 2*tig;
            float2 bb = *(const float2*)&bias[cc];
            if (mode == 0) {
                float2 o0, o1;
                o0.x = ac[0]*scale + bb.x;  o0.y = ac[1]*scale + bb.y;
                o1.x = ac[2]*scale + bb.x;  o1.y = ac[3]*scale + bb.y;
                float2 q0 = *(const float2*)&resid[r0*512 + cc];
                float2 q1 = *(const float2*)&resid[(r0+8)*512 + cc];
                o0.x += q0.x; o0.y += q0.y;
                o1.x += q1.x; o1.y += q1.y;
                *(float2*)&C[r0*512 + cc]     = o0;
                *(float2*)&C[(r0+8)*512 + cc] = o1;
            } else if (mode == 1) {
                uint32_t h, l;
                bsplit2((ac[0] + bb.x)*scale, (ac[1] + bb.y)*scale, h, l);
                *(uint32_t*)&Hd[r0*512 + cc] = h;
                *(uint32_t*)&Ld[r0*512 + cc] = l;
                bsplit2((ac[2] + bb.x)*scale, (ac[3] + bb.y)*scale, h, l);
                *(uint32_t*)&Hd[(r0+8)*512 + cc] = h;
                *(uint32_t*)&Ld[(r0+8)*512 + cc] = l;
            } else {
#pragma unroll
                for (int e = 0; e < 4; e++) {
                    int r  = (e < 2) ? r0 : r0 + 8;
                    int cx = cc + (e & 1);
                    float o = ac[e] + ((e & 1) ? bb.y : bb.x);
                    int cb = r >> 9, t = r & 511;
                    int hh = cx >> 6, dv = cx & 63;
                    int addr = (((cb*8 + hh)*64) + dv)*512 + t;
                    __nv_bfloat16 bh16 = __float2bfloat16_rn(o);
                    __nv_bfloat16 bl16 =
                        __float2bfloat16_rn(o - __bfloat162float(bh16));
                    Hd[addr] = bh16; Ld[addr] = bl16;
                }
            }
        }
}

__global__ __launch_bounds__(256) void hmma_qkv(
    const float* __restrict__ bq, const float* __restrict__ bk,
    const float* __restrict__ bv)
{
    int w = blockIdx.z;
    if (w == 0)
        hmma_gemm_body(g_xh, g_xl, g_wh, g_wl, bq, nullptr,
                       0.125f, 1, nullptr, g_qh, g_ql);
    else if (w == 1)
        hmma_gemm_body(g_xh, g_xl, g_wh + DD*DD, g_wl + DD*DD, bk, nullptr,
                       1.0f, 1, nullptr, g_kh, g_kl);
    else
        hmma_gemm_body(g_xh, g_xl, g_wh + 2*DD*DD, g_wl + 2*DD*DD, bv, nullptr,
                       1.0f, 2, nullptr, g_vTh, g_vTl);
}

__global__ __launch_bounds__(256) void hmma_out(
    const float* __restrict__ bo, const float* __restrict__ x)
{
    hmma_gemm_body(g_ctxh, g_ctxl, g_wh + 3*DD*DD, g_wl + 3*DD*DD,
                   bo, x, 1.0f / (float)NVAR, 0, g_res, nullptr, nullptr);
}

// ---------------------------------------------------------------------------
// FA2-style mma.sync attention, cp.async double-buffered.
// Block = 128 thr (4 warps), 64 Q rows, one (qb, h). Smaller blocks ->
// 3 blocks/SM resident (reg-bound at 256 thr gave only 1) -> 12 warps/SM.
// ---------------------------------------------------------------------------
#define ALD 72
#define KSZ (64*ALD*2)         // 9216 B per array
#define ASTAGE (4*KSZ)         // 36864 B
#define ASMEM (2*ASTAGE)       // 73728 B

__global__ __launch_bounds__(128) void attn_mma_kernel()
{
    extern __shared__ char asm_sm[];
    const uint32_t smb = smem_u32(asm_sm);

    const int tid  = threadIdx.x;
    const int lane = tid & 31;
    const int warp = tid >> 5;           // 0..3
    const int g    = lane >> 2;
    const int tig  = lane & 3;
    const int t0   = blockIdx.x * 64;
    const int h    = blockIdx.y;
    const int qb   = blockIdx.z;
    const int b    = qb & (BB - 1);

    // persistent Q fragments
    uint32_t qfh[4][4], qfl[4][4];
    {
        const int qrow = qb*512 + t0 + warp*16 + g;
#pragma unroll
        for (int kc = 0; kc < 4; kc++) {
            int base = qrow*512 + h*64 + kc*16 + 2*tig;
            qfh[kc][0] = *(const uint32_t*)&g_qh[base];
            qfh[kc][1] = *(const uint32_t*)&g_qh[base + 8*512];
            qfh[kc][2] = *(const uint32_t*)&g_qh[base + 8];
            qfh[kc][3] = *(const uint32_t*)&g_qh[base + 8*512 + 8];
            qfl[kc][0] = *(const uint32_t*)&g_ql[base];
            qfl[kc][1] = *(const uint32_t*)&g_ql[base + 8*512];
            qfl[kc][2] = *(const uint32_t*)&g_ql[base + 8];
            qfl[kc][3] = *(const uint32_t*)&g_ql[base + 8*512 + 8];
        }
    }

#define A_ISSUE(ti, st) do {                                                  \
    int c_ = (ti) >> 3, s0_ = ((ti) & 7) * 64;                                \
    int kt_ = (c_*BB + b)*512;                                                \
    int vr_ = ((c_*BB + b)*HH + h)*64;                                        \
    uint32_t b0 = smb + (st)*ASTAGE;                                          \
    _Pragma("unroll")                                                         \
    for (int r_ = 0; r_ < 4; r_++) {                                          \
        int idx_ = tid + 128*r_;                                              \
        int row_ = idx_ >> 3, seg_ = idx_ & 7;                                \
        uint32_t o_ = (row_*ALD + seg_*8)*2;                                  \
        cp16(b0 + o_,         &g_kh [(kt_ + s0_ + row_)*512 + h*64 + seg_*8]);\
        cp16(b0 + KSZ + o_,   &g_kl [(kt_ + s0_ + row_)*512 + h*64 + seg_*8]);\
        cp16(b0 + 2*KSZ + o_, &g_vTh[(vr_ + row_)*512 + s0_ + seg_*8]);       \
        cp16(b0 + 3*KSZ + o_, &g_vTl[(vr_ + row_)*512 + s0_ + seg_*8]);       \
    }                                                                         \
} while (0)

    float of[8][4], oa[8][4];
    float m0 = -1e30f, m1 = -1e30f, l0 = 0.f, l1 = 0.f;
#pragma unroll
    for (int j = 0; j < 8; j++)
#pragma unroll
        for (int r = 0; r < 4; r++) { of[j][r] = 0.f; oa[j][r] = 0.f; }

    A_ISSUE(0, 0); CP_COMMIT();

    for (int ti = 0; ti < 32; ti++) {
        if (ti + 1 < 32) { A_ISSUE(ti+1, (ti+1)&1); CP_COMMIT(); CP_WAIT(1); }
        else CP_WAIT(0);
        __syncthreads();

        const char* st = asm_sm + (ti & 1)*ASTAGE;
        const __nv_bfloat16* kh = (const __nv_bfloat16*)st;
        const __nv_bfloat16* kl = (const __nv_bfloat16*)(st + KSZ);
        const __nv_bfloat16* vh = (const __nv_bfloat16*)(st + 2*KSZ);
        const __nv_bfloat16* vl = (const __nv_bfloat16*)(st + 3*KSZ);

        // S = Q@K^T
        float sf[8][4];
#pragma unroll
        for (int j = 0; j < 8; j++)
#pragma unroll
            for (int r = 0; r < 4; r++) sf[j][r] = 0.f;
#pragma unroll
        for (int kc = 0; kc < 4; kc++) {
#pragma unroll
            for (int j = 0; j < 8; j++) {
                const int ro = (j*8 + g)*ALD + kc*16 + 2*tig;
                uint32_t bfr[2], bfl[2];
                bfr[0] = *(const uint32_t*)&kh[ro];
                bfr[1] = *(const uint32_t*)&kh[ro + 8];
                bfl[0] = *(const uint32_t*)&kl[ro];
                bfl[1] = *(const uint32_t*)&kl[ro + 8];
                mma_bf16(sf[j], qfh[kc], bfr);
                mma_bf16(sf[j], qfl[kc], bfr);
                mma_bf16(sf[j], qfh[kc], bfl);
            }
        }

        // online softmax
        float mx0 = -1e30f, mx1 = -1e30f;
#pragma unroll
        for (int j = 0; j < 8; j++) {
            mx0 = fmaxf(mx0, fmaxf(sf[j][0], sf[j][1]));
            mx1 = fmaxf(mx1, fmaxf(sf[j][2], sf[j][3]));
        }
        mx0 = fmaxf(mx0, __shfl_xor_sync(0xffffffffu, mx0, 1));
        mx0 = fmaxf(mx0, __shfl_xor_sync(0xffffffffu, mx0, 2));
        mx1 = fmaxf(mx1, __shfl_xor_sync(0xffffffffu, mx1, 1));
        mx1 = fmaxf(mx1, __shfl_xor_sync(0xffffffffu, mx1, 2));
        float mn0 = fmaxf(m0, mx0), mn1 = fmaxf(m1, mx1);
        float cr_0 = __expf(m0 - mn0), cr_1 = __expf(m1 - mn1);
        float rs0 = 0.f, rs1 = 0.f;
#pragma unroll
        for (int j = 0; j < 8; j++) {
            sf[j][0] = __expf(sf[j][0] - mn0);
            sf[j][1] = __expf(sf[j][1] - mn0);
            sf[j][2] = __expf(sf[j][2] - mn1);
            sf[j][3] = __expf(sf[j][3] - mn1);
            rs0 += sf[j][0] + sf[j][1];
            rs1 += sf[j][2] + sf[j][3];
        }
        rs0 += __shfl_xor_sync(0xffffffffu, rs0, 1);
        rs0 += __shfl_xor_sync(0xffffffffu, rs0, 2);
        rs1 += __shfl_xor_sync(0xffffffffu, rs1, 1);
        rs1 += __shfl_xor_sync(0xffffffffu, rs1, 2);
        l0 = l0*cr_0 + rs0; m0 = mn0;
        l1 = l1*cr_1 + rs1; m1 = mn1;
#pragma unroll
        for (int j = 0; j < 8; j++) {
            of[j][0] *= cr_0; of[j][1] *= cr_0;
            of[j][2] *= cr_1; of[j][3] *= cr_1;
        }

        // O += P@V
#pragma unroll
        for (int kc = 0; kc < 4; kc++) {
            uint32_t ph[4], pl[4];
            bsplit2(sf[2*kc  ][0], sf[2*kc  ][1], ph[0], pl[0]);
            bsplit2(sf[2*kc  ][2], sf[2*kc  ][3], ph[1], pl[1]);
            bsplit2(sf[2*kc+1][0], sf[2*kc+1][1], ph[2], pl[2]);
            bsplit2(sf[2*kc+1][2], sf[2*kc+1][3], ph[3], pl[3]);
#pragma unroll
            for (int j = 0; j < 8; j++) {
                const int ro = (j*8 + g)*ALD + kc*16 + 2*tig;
                uint32_t bfr[2], bfl[2];
                bfr[0] = *(const uint32_t*)&vh[ro];
                bfr[1] = *(const uint32_t*)&vh[ro + 8];
                bfl[0] = *(const uint32_t*)&vl[ro];
                bfl[1] = *(const uint32_t*)&vl[ro + 8];
                mma_bf16(of[j], ph, bfr);
                mma_bf16(of[j], pl, bfr);
                mma_bf16(of[j], ph, bfl);
            }
        }

        if ((ti & 7) == 7) {   // fold this key-variable
            float i0 = 1.f / l0, i1 = 1.f / l1;
#pragma unroll
            for (int j = 0; j < 8; j++) {
                oa[j][0] += of[j][0]*i0; oa[j][1] += of[j][1]*i0;
                oa[j][2] += of[j][2]*i1; oa[j][3] += of[j][3]*i1;
                of[j][0] = of[j][1] = of[j][2] = of[j][3] = 0.f;
            }
            m0 = m1 = -1e30f; l0 = l1 = 0.f;
        }
        __syncthreads();
    }

    // write ctx_sum split
    const int orow = qb*512 + t0 + warp*16 + g;
#pragma unroll
    for (int j = 0; j < 8; j++) {
        int addr = orow*512 + h*64 + j*8 + 2*tig;
        uint32_t hb, lb;
        bsplit2(oa[j][0], oa[j][1], hb, lb);
        *(uint32_t*)&g_ctxh[addr] = hb;
        *(uint32_t*)&g_ctxl[addr] = lb;
        bsplit2(oa[j][2], oa[j][3], hb, lb);
        *(uint32_t*)&g_ctxh[addr + 8*512] = hb;
        *(uint32_t*)&g_ctxl[addr + 8*512] = lb;
    }
}

// ---------------------------------------------------------------------------
// LayerNorm
// ---------------------------------------------------------------------------
__global__ __launch_bounds__(128) void ln_kernel(const float* __restrict__ gamma,
                                                 const float* __restrict__ beta,
                                                 float* __restrict__ out)
{
    const int row = blockIdx.x;
    const int t = threadIdx.x;
    float4 v = *(const float4*)&g_res[row*512 + t*4];
    float s  = v.x + v.y + v.z + v.w;
    float ss = v.x*v.x + v.y*v.y + v.z*v.z + v.w*v.w;
#pragma unroll
    for (int off = 16; off; off >>= 1) {
        s  += __shfl_xor_sync(0xffffffffu, s, off);
        ss += __shfl_xor_sync(0xffffffffu, ss, off);
    }
    __shared__ float as[4], ass[4];
    if ((t & 31) == 0) { as[t >> 5] = s; ass[t >> 5] = ss; }
    __syncthreads();
    s  = as[0] + as[1] + as[2] + as[3];
    ss = ass[0] + ass[1] + ass[2] + ass[3];
    float mu  = s * (1.f / 512.f);
    float var = ss * (1.f / 512.f) - mu * mu;
    float inv = rsqrtf(var + 1e-5f);
    float4 gg = *(const float4*)&gamma[t*4];
    float4 bb = *(const float4*)&beta[t*4];
    float4 o4;
    o4.x = (v.x - mu)*inv*gg.x + bb.x;
    o4.y = (v.y - mu)*inv*gg.y + bb.y;
    o4.z = (v.z - mu)*inv*gg.z + bb.z;
    o4.w = (v.w - mu)*inv*gg.w + bb.w;
    *(float4*)&out[row*512 + t*4] = o4;
}

extern "C" void kernel_launch(void* const* d_in, const int* in_sizes, int n_in,
                              void* d_out, int out_size)
{
    const float* x     = (const float*)d_in[0];
    const float* Wq    = (const float*)d_in[1];
    const float* bq    = (const float*)d_in[2];
    const float* Wk    = (const float*)d_in[3];
    const float* bk    = (const float*)d_in[4];
    const float* Wv    = (const float*)d_in[5];
    const float* bv    = (const float*)d_in[6];
    const float* Wo    = (const float*)d_in[7];
    const float* bo    = (const float*)d_in[8];
    const float* gamma = (const float*)d_in[9];
    const float* beta  = (const float*)d_in[10];
    float* out = (float*)d_out;

    cudaFuncSetAttribute(attn_mma_kernel,
                         cudaFuncAttributeMaxDynamicSharedMemorySize, ASMEM);
    cudaFuncSetAttribute(hmma_qkv,
                         cudaFuncAttributeMaxDynamicSharedMemorySize, GSMEM);
    cudaFuncSetAttribute(hmma_out,
                         cudaFuncAttributeMaxDynamicSharedMemorySize, GSMEM);

    prep_x_kernel<<<MROWS*DD/4/256, 256>>>(x);
    prep_w_kernel<<<dim3(16, 16, 4), dim3(32, 8)>>>(Wq, Wk, Wv, Wo);
    hmma_qkv<<<dim3(512/64, MROWS/128, 3), 256, GSMEM>>>(bq, bk, bv);
    attn_mma_kernel<<<dim3(TT/64, HH, NVAR*BB), 128, ASMEM>>>();
    hmma_out<<<dim3(512/64, MROWS/128, 1), 256, GSMEM>>>(bo, x);
    ln_kernel<<<MROWS, 128>>>(gamma, beta, out);
}